// round 10
// baseline (speedup 1.0000x reference)
#include <cuda_runtime.h>
#include <cuda_fp16.h>

#define TM 32
#define EPS 1e-5f

#define SA1H 72    // [32][72] halves: row step 144B == 16B mod 128B (LDSM-clean)
#define SA2H 264   // [32][264] halves: row step 528B == 16B mod 128B
#define PS_STRIDE 9

// ---------------- device scratch ----------------
__device__ __align__(16) __half g_phonePh[100 * 256];   // fp16 folded phone table
__device__ __align__(16) __half g_midiPh[128 * 256];    // fp16 folded midi table
__device__ __align__(16) float g_bias[256];
// fp16 fragment-packed B: [kt16][n=256][16 halves]; lane q reads halves
// [q*4 .. q*4+3] = k elements {2q, 2q+1, 2q+8, 2q+9} of that 16-k tile (one 8B read).
__device__ __align__(16) __half g_W1H[4 * 256 * 16];    // K=64  -> 4 k-tiles
__device__ __align__(16) __half g_W2H[16 * 256 * 16];   // K=256 -> 16 k-tiles

__host__ __device__ __forceinline__ int slot16(int kk) {
    return ((kk & 7) >> 1) * 4 + ((kk >> 3) & 1) * 2 + (kk & 1);
}

__device__ __forceinline__ unsigned smem_u32(const void* p) {
    unsigned a;
    asm("{ .reg .u64 t; cvta.to.shared.u64 t, %1; cvt.u32.u64 %0, t; }"
        : "=r"(a) : "l"(p));
    return a;
}

__device__ __forceinline__ void ldsm_x4(unsigned& r0, unsigned& r1,
                                        unsigned& r2, unsigned& r3,
                                        unsigned addr) {
    asm volatile("ldmatrix.sync.aligned.m8n8.x4.shared.b16 {%0,%1,%2,%3}, [%4];"
                 : "=r"(r0), "=r"(r1), "=r"(r2), "=r"(r3) : "r"(addr));
}

__device__ __forceinline__ void mma_f16(float* c, const unsigned* a,
                                        const unsigned* b) {
    asm volatile(
        "mma.sync.aligned.m16n8k16.row.col.f32.f16.f16.f32 "
        "{%0,%1,%2,%3}, {%4,%5,%6,%7}, {%8,%9}, {%0,%1,%2,%3};"
        : "+f"(c[0]), "+f"(c[1]), "+f"(c[2]), "+f"(c[3])
        : "r"(a[0]), "r"(a[1]), "r"(a[2]), "r"(a[3]), "r"(b[0]), "r"(b[1]));
}

// ---------------- precompute (4 independent accumulators: short dep chains) ----
__global__ void precompute_kernel(
    const float* __restrict__ f0_w2, const float* __restrict__ f0_b2,
    const float* __restrict__ phone_table, const float* __restrict__ midi_table,
    const float* __restrict__ dur_w2, const float* __restrict__ dur_b2,
    const float* __restrict__ proj_w1, const float* __restrict__ proj_b1,
    const float* __restrict__ proj_w2) {
    const int r = blockIdx.x;
    const int c = threadIdx.x;
    if (r < 100) {
        float s0 = 0.f, s1 = 0.f, s2 = 0.f, s3 = 0.f;
        #pragma unroll 8
        for (int k = 0; k < 128; k += 4) {
            s0 += phone_table[r * 128 + k + 0] * proj_w1[(64 + k + 0) * 256 + c];
            s1 += phone_table[r * 128 + k + 1] * proj_w1[(64 + k + 1) * 256 + c];
            s2 += phone_table[r * 128 + k + 2] * proj_w1[(64 + k + 2) * 256 + c];
            s3 += phone_table[r * 128 + k + 3] * proj_w1[(64 + k + 3) * 256 + c];
        }
        g_phonePh[r * 256 + c] = __float2half_rn((s0 + s1) + (s2 + s3));
    } else if (r < 228) {
        const int m = r - 100;
        float s0 = 0.f, s1 = 0.f, s2 = 0.f, s3 = 0.f;
        #pragma unroll 4
        for (int k = 0; k < 64; k += 4) {
            s0 += midi_table[m * 64 + k + 0] * proj_w1[(192 + k + 0) * 256 + c];
            s1 += midi_table[m * 64 + k + 1] * proj_w1[(192 + k + 1) * 256 + c];
            s2 += midi_table[m * 64 + k + 2] * proj_w1[(192 + k + 2) * 256 + c];
            s3 += midi_table[m * 64 + k + 3] * proj_w1[(192 + k + 3) * 256 + c];
        }
        g_midiPh[m * 256 + c] = __float2half_rn((s0 + s1) + (s2 + s3));
    } else if (r < 260) {
        const int kd = r - 228;          // derived-K 0..31 (f0 part)
        float s0 = 0.f, s1 = 0.f, s2 = 0.f, s3 = 0.f;
        #pragma unroll 4
        for (int k = 0; k < 64; k += 4) {
            s0 += f0_w2[kd * 64 + k + 0] * proj_w1[(k + 0) * 256 + c];
            s1 += f0_w2[kd * 64 + k + 1] * proj_w1[(k + 1) * 256 + c];
            s2 += f0_w2[kd * 64 + k + 2] * proj_w1[(k + 2) * 256 + c];
            s3 += f0_w2[kd * 64 + k + 3] * proj_w1[(k + 3) * 256 + c];
        }
        g_W1H[((kd >> 4) * 256 + c) * 16 + slot16(kd & 15)] =
            __float2half_rn((s0 + s1) + (s2 + s3));
    } else if (r < 292) {
        const int j = r - 260;           // dur part -> derived-K 32..63
        const int kd = 32 + j;
        float s0 = 0.f, s1 = 0.f, s2 = 0.f, s3 = 0.f;
        #pragma unroll 4
        for (int k = 0; k < 64; k += 4) {
            s0 += dur_w2[j * 64 + k + 0] * proj_w1[(256 + k + 0) * 256 + c];
            s1 += dur_w2[j * 64 + k + 1] * proj_w1[(256 + k + 1) * 256 + c];
            s2 += dur_w2[j * 64 + k + 2] * proj_w1[(256 + k + 2) * 256 + c];
            s3 += dur_w2[j * 64 + k + 3] * proj_w1[(256 + k + 3) * 256 + c];
        }
        g_W1H[((kd >> 4) * 256 + c) * 16 + slot16(kd & 15)] =
            __float2half_rn((s0 + s1) + (s2 + s3));
    } else if (r < 293) {
        float s = proj_b1[c];
        #pragma unroll 4
        for (int k = 0; k < 64; k++) {
            s += f0_b2[k] * proj_w1[k * 256 + c];
            s += dur_b2[k] * proj_w1[(256 + k) * 256 + c];
        }
        g_bias[c] = s;
    } else {
        const int k = r - 293;           // 0..255: proj_w2 input-row k, col c
        g_W2H[((k >> 4) * 256 + c) * 16 + slot16(k & 15)] =
            __float2half_rn(proj_w2[k * 256 + c]);
    }
}

// ---------------- main fused fp16-mma kernel (3 CTAs/SM, TM=32) ----------------
__global__ __launch_bounds__(256, 3)
void cond_enc_mma_kernel(
    const float* __restrict__ f0, const int* __restrict__ phone,
    const float* __restrict__ duration, const int* __restrict__ midi,
    const float* __restrict__ f0_w1, const float* __restrict__ f0_b1,
    const float* __restrict__ dur_w1, const float* __restrict__ dur_b1,
    const float* __restrict__ ln_g, const float* __restrict__ ln_b,
    const float* __restrict__ proj_b2,
    float* __restrict__ out, int npos) {
    extern __shared__ __align__(16) char smraw[];
    __half* sa1 = (__half*)smraw;                       // [32][72]
    __half* sA2 = sa1 + 32 * SA1H;                      // [32][264]
    float2* sPS = (float2*)(sA2 + 32 * SA2H);           // [32][9] partials
    float2* sMV = sPS + 32 * PS_STRIDE;                 // [32] (mu, rs)
    float* sbias = (float*)(sMV + 32);                  // [256]
    float* sg = sbias + 256;
    float* sb = sg + 256;
    float* sb2 = sb + 256;

    const int tid = threadIdx.x;
    const int lane = tid & 31;
    const int w = tid >> 5;          // warp w owns cols [w*32, w*32+32), all 32 rows
    const int n0w = w * 32;
    const int gid = lane >> 2;
    const int q = lane & 3;
    const int base = blockIdx.x * TM;

    // ldmatrix per-lane A offsets (b16, 16-k tiles)
    const int tA = lane >> 3;
    const int aRow = (lane & 7) + (tA & 1) * 8;
    const int aKof = (tA >> 1) * 8;       // halves

    const unsigned u_sa1 = smem_u32(sa1);
    const unsigned u_sA2 = smem_u32(sA2);

    const uint2* __restrict__ W1H = (const uint2*)g_W1H;
    const uint2* __restrict__ W2H = (const uint2*)g_W2H;
    int nIdx[4];
    #pragma unroll
    for (int nt = 0; nt < 4; nt++) nIdx[nt] = n0w + nt * 8 + gid;

    sbias[tid] = g_bias[tid];
    sg[tid] = ln_g[tid];
    sb[tid] = ln_b[tid];
    sb2[tid] = proj_b2[tid];

    // Phase 1: tiny MLPs -> sa1 (half2 stores)
    for (int idx = tid; idx < TM * 32; idx += 256) {
        const int t = idx >> 5;
        const int u = (idx & 31) * 2;
        int row = base + t; if (row >= npos) row = npos - 1;
        float v0, v1;
        if (u < 32) {
            const float fv = f0[row];
            v0 = fv * f0_w1[u] + f0_b1[u];
            v1 = fv * f0_w1[u + 1] + f0_b1[u + 1];
        } else {
            const float dv = duration[row];
            v0 = dv * dur_w1[u - 32] + dur_b1[u - 32];
            v1 = dv * dur_w1[u - 31] + dur_b1[u - 31];
        }
        *(__half2*)&sa1[t * SA1H + u] =
            __floats2half2_rn(fmaxf(v0, 0.f), fmaxf(v1, 0.f));
    }
    __syncthreads();   // (1) sa1 ready

    float acc[2][4][4];
    #pragma unroll
    for (int mt = 0; mt < 2; mt++)
        #pragma unroll
        for (int nt = 0; nt < 4; nt++)
            #pragma unroll
            for (int e = 0; e < 4; e++) acc[mt][nt][e] = 0.f;

    // Phase 2: GEMM1 (K=64 -> 4 fp16 k-tiles), B direct from L2
    {
        uint2 bq[2][4];
        #pragma unroll
        for (int nt = 0; nt < 4; nt++)
            bq[0][nt] = W1H[(0 * 256 + nIdx[nt]) * 4 + q];
        #pragma unroll
        for (int kt = 0; kt < 4; kt++) {
            const int cur = kt & 1, nxt = cur ^ 1;
            if (kt < 3) {
                #pragma unroll
                for (int nt = 0; nt < 4; nt++)
                    bq[nxt][nt] = W1H[((kt + 1) * 256 + nIdx[nt]) * 4 + q];
            }
            unsigned a[2][4];
            #pragma unroll
            for (int mt = 0; mt < 2; mt++)
                ldsm_x4(a[mt][0], a[mt][1], a[mt][2], a[mt][3],
                        u_sa1 + (unsigned)((mt * 16 + aRow) * SA1H +
                                           kt * 16 + aKof) * 2u);
            #pragma unroll
            for (int mt = 0; mt < 2; mt++)
                #pragma unroll
                for (int nt = 0; nt < 4; nt++)
                    mma_f16(acc[mt][nt], a[mt], (const unsigned*)&bq[cur][nt]);
        }
    }

    // Phase 3a: add bias + fp16 phone/midi table contributions in-register,
    // accumulate per-row partial sums for LayerNorm.
    {
        #pragma unroll
        for (int mt = 0; mt < 2; mt++) {
            const int r0 = mt * 16 + gid;
            const int r1 = r0 + 8;
            int g0 = base + r0; if (g0 >= npos) g0 = npos - 1;
            int g1 = base + r1; if (g1 >= npos) g1 = npos - 1;
            const __half* __restrict__ pp0 = &g_phonePh[phone[g0] * 256];
            const __half* __restrict__ mp0 = &g_midiPh[midi[g0] * 256];
            const __half* __restrict__ pp1 = &g_phonePh[phone[g1] * 256];
            const __half* __restrict__ mp1 = &g_midiPh[midi[g1] * 256];
            float s0 = 0.f, ss0 = 0.f, s1 = 0.f, ss1 = 0.f;
            #pragma unroll
            for (int nt = 0; nt < 4; nt++) {
                const int col = n0w + nt * 8 + q * 2;
                const float2 bb = *(const float2*)&sbias[col];
                const float2 a0 = __half22float2(*(const __half2*)&pp0[col]);
                const float2 b0 = __half22float2(*(const __half2*)&mp0[col]);
                const float2 a1 = __half22float2(*(const __half2*)&pp1[col]);
                const float2 b1 = __half22float2(*(const __half2*)&mp1[col]);
                float x0 = acc[mt][nt][0] + bb.x + a0.x + b0.x;
                float x1 = acc[mt][nt][1] + bb.y + a0.y + b0.y;
                float x2 = acc[mt][nt][2] + bb.x + a1.x + b1.x;
                float x3 = acc[mt][nt][3] + bb.y + a1.y + b1.y;
                acc[mt][nt][0] = x0; acc[mt][nt][1] = x1;
                acc[mt][nt][2] = x2; acc[mt][nt][3] = x3;
                s0 += x0 + x1; ss0 += x0 * x0 + x1 * x1;
                s1 += x2 + x3; ss1 += x2 * x2 + x3 * x3;
            }
            #pragma unroll
            for (int o = 1; o < 4; o <<= 1) {
                s0 += __shfl_xor_sync(0xffffffffu, s0, o);
                ss0 += __shfl_xor_sync(0xffffffffu, ss0, o);
                s1 += __shfl_xor_sync(0xffffffffu, s1, o);
                ss1 += __shfl_xor_sync(0xffffffffu, ss1, o);
            }
            if (q == 0) {
                sPS[r0 * PS_STRIDE + w] = make_float2(s0, ss0);
                sPS[r1 * PS_STRIDE + w] = make_float2(s1, ss1);
            }
        }
    }
    __syncthreads();   // (2) partials ready

    // Phase 3b: finalize mu/rs per row (threads 0..31)
    if (tid < 32) {
        float s = 0.f, ss = 0.f;
        #pragma unroll
        for (int j = 0; j < 8; j++) {
            const float2 ps = sPS[tid * PS_STRIDE + j];
            s += ps.x; ss += ps.y;
        }
        const float mu = s * (1.f / 256.f);
        float var = ss * (1.f / 256.f) - mu * mu;
        var = fmaxf(var, 0.f);
        sMV[tid] = make_float2(mu, rsqrtf(var + EPS));
    }
    __syncthreads();   // (3) mu/rs ready

    // Phase 3c: apply LN + ReLU in-register, write half A2 tile
    {
        #pragma unroll
        for (int mt = 0; mt < 2; mt++) {
            const int r0 = mt * 16 + gid;
            const int r1 = r0 + 8;
            const float2 mv0 = sMV[r0];
            const float2 mv1 = sMV[r1];
            #pragma unroll
            for (int nt = 0; nt < 4; nt++) {
                const int col = n0w + nt * 8 + q * 2;
                const float2 gg = *(const float2*)&sg[col];
                const float2 bb = *(const float2*)&sb[col];
                float x0 = fmaxf((acc[mt][nt][0] - mv0.x) * mv0.y * gg.x + bb.x, 0.f);
                float x1 = fmaxf((acc[mt][nt][1] - mv0.x) * mv0.y * gg.y + bb.y, 0.f);
                float x2 = fmaxf((acc[mt][nt][2] - mv1.x) * mv1.y * gg.x + bb.x, 0.f);
                float x3 = fmaxf((acc[mt][nt][3] - mv1.x) * mv1.y * gg.y + bb.y, 0.f);
                *(__half2*)&sA2[r0 * SA2H + col] = __floats2half2_rn(x0, x1);
                *(__half2*)&sA2[r1 * SA2H + col] = __floats2half2_rn(x2, x3);
            }
        }
    }
    __syncthreads();   // (4) A2 ready

    #pragma unroll
    for (int mt = 0; mt < 2; mt++)
        #pragma unroll
        for (int nt = 0; nt < 4; nt++)
            #pragma unroll
            for (int e = 0; e < 4; e++) acc[mt][nt][e] = 0.f;

    // Phase 4: GEMM2 (K=256 -> 16 fp16 k-tiles), barrier-free, B from L2
    {
        uint2 bq[2][4];
        #pragma unroll
        for (int nt = 0; nt < 4; nt++)
            bq[0][nt] = W2H[(0 * 256 + nIdx[nt]) * 4 + q];
        #pragma unroll 4
        for (int kt = 0; kt < 16; kt++) {
            const int cur = kt & 1, nxt = cur ^ 1;
            if (kt < 15) {
                #pragma unroll
                for (int nt = 0; nt < 4; nt++)
                    bq[nxt][nt] = W2H[((kt + 1) * 256 + nIdx[nt]) * 4 + q];
            }
            unsigned a[2][4];
            #pragma unroll
            for (int mt = 0; mt < 2; mt++)
                ldsm_x4(a[mt][0], a[mt][1], a[mt][2], a[mt][3],
                        u_sA2 + (unsigned)((mt * 16 + aRow) * SA2H +
                                           kt * 16 + aKof) * 2u);
            #pragma unroll
            for (int mt = 0; mt < 2; mt++)
                #pragma unroll
                for (int nt = 0; nt < 4; nt++)
                    mma_f16(acc[mt][nt], a[mt], (const unsigned*)&bq[cur][nt]);
        }
    }

    // Phase 5: write output (+proj_b2)
    #pragma unroll
    for (int mt = 0; mt < 2; mt++) {
        const int row = mt * 16 + gid;
        #pragma unroll
        for (int nt = 0; nt < 4; nt++) {
            const int col = n0w + nt * 8 + q * 2;
            const float b2a = sb2[col];
            const float b2b = sb2[col + 1];
            if (base + row < npos)
                *(float2*)&out[(size_t)(base + row) * 256 + col] =
                    make_float2(acc[mt][nt][0] + b2a, acc[mt][nt][1] + b2b);
            if (base + row + 8 < npos)
                *(float2*)&out[(size_t)(base + row + 8) * 256 + col] =
                    make_float2(acc[mt][nt][2] + b2a, acc[mt][nt][3] + b2b);
        }
    }
}

extern "C" void kernel_launch(void* const* d_in, const int* in_sizes, int n_in,
                              void* d_out, int out_size) {
    const float* f0          = (const float*)d_in[0];
    const int*   phone       = (const int*)  d_in[1];
    const float* duration    = (const float*)d_in[2];
    const int*   midi        = (const int*)  d_in[3];
    const float* f0_w1       = (const float*)d_in[4];
    const float* f0_b1       = (const float*)d_in[5];
    const float* f0_w2       = (const float*)d_in[6];
    const float* f0_b2       = (const float*)d_in[7];
    const float* phone_table = (const float*)d_in[8];
    const float* midi_table  = (const float*)d_in[9];
    const float* dur_w1      = (const float*)d_in[10];
    const float* dur_b1      = (const float*)d_in[11];
    const float* dur_w2      = (const float*)d_in[12];
    const float* dur_b2      = (const float*)d_in[13];
    const float* proj_w1     = (const float*)d_in[14];
    const float* proj_b1     = (const float*)d_in[15];
    const float* ln_g        = (const float*)d_in[16];
    const float* ln_b        = (const float*)d_in[17];
    const float* proj_w2     = (const float*)d_in[18];
    const float* proj_b2     = (const float*)d_in[19];
    float* out = (float*)d_out;
    const int npos = in_sizes[0];

    precompute_kernel<<<549, 256>>>(f0_w2, f0_b2, phone_table, midi_table,
                                    dur_w2, dur_b2, proj_w1, proj_b1, proj_w2);

    const size_t smem_bytes =
        (size_t)(32 * SA1H + 32 * SA2H) * sizeof(__half) +
        (size_t)(32 * PS_STRIDE + 32) * sizeof(float2) +
        (size_t)(4 * 256) * sizeof(float) + 64;
    cudaFuncSetAttribute(cond_enc_mma_kernel,
                         cudaFuncAttributeMaxDynamicSharedMemorySize,
                         (int)smem_bytes);
    const int grid = (npos + TM - 1) / TM;
    cond_enc_mma_kernel<<<grid, 256, smem_bytes>>>(
        f0, phone, duration, midi, f0_w1, f0_b1, dur_w1, dur_b1,
        ln_g, ln_b, proj_b2, out, npos);
}

// round 11
// speedup vs baseline: 1.1170x; 1.1170x over previous
#include <cuda_runtime.h>
#include <cuda_fp16.h>

#define TM 64
#define EPS 1e-5f

#define SA1H 72    // [64][72] halves: row step 144B == 16B mod 128B (LDSM-clean)
#define SA2H 264   // [64][264] halves: row step 528B == 16B mod 128B
#define PS_STRIDE 9

// ---------------- device scratch ----------------
__device__ __align__(16) __half g_phonePh[100 * 256];   // fp16 folded phone table
__device__ __align__(16) __half g_midiPh[128 * 256];    // fp16 folded midi table
__device__ __align__(16) float g_bias[256];
// fp16 fragment-packed B: [kt16][n=256][16 halves]; lane q reads halves
// [q*4 .. q*4+3] = k elements {2q, 2q+1, 2q+8, 2q+9} of that 16-k tile (one 8B read).
__device__ __align__(16) __half g_W1H[4 * 256 * 16];    // K=64  -> 4 k-tiles
__device__ __align__(16) __half g_W2H[16 * 256 * 16];   // K=256 -> 16 k-tiles

__host__ __device__ __forceinline__ int slot16(int kk) {
    return ((kk & 7) >> 1) * 4 + ((kk >> 3) & 1) * 2 + (kk & 1);
}

__device__ __forceinline__ unsigned smem_u32(const void* p) {
    unsigned a;
    asm("{ .reg .u64 t; cvta.to.shared.u64 t, %1; cvt.u32.u64 %0, t; }"
        : "=r"(a) : "l"(p));
    return a;
}

__device__ __forceinline__ void ldsm_x4(unsigned& r0, unsigned& r1,
                                        unsigned& r2, unsigned& r3,
                                        unsigned addr) {
    asm volatile("ldmatrix.sync.aligned.m8n8.x4.shared.b16 {%0,%1,%2,%3}, [%4];"
                 : "=r"(r0), "=r"(r1), "=r"(r2), "=r"(r3) : "r"(addr));
}

__device__ __forceinline__ void mma_f16(float* c, const unsigned* a,
                                        const unsigned* b) {
    asm volatile(
        "mma.sync.aligned.m16n8k16.row.col.f32.f16.f16.f32 "
        "{%0,%1,%2,%3}, {%4,%5,%6,%7}, {%8,%9}, {%0,%1,%2,%3};"
        : "+f"(c[0]), "+f"(c[1]), "+f"(c[2]), "+f"(c[3])
        : "r"(a[0]), "r"(a[1]), "r"(a[2]), "r"(a[3]), "r"(b[0]), "r"(b[1]));
}

// ---------------- precompute (4 independent accumulators: short dep chains) ----
__global__ void precompute_kernel(
    const float* __restrict__ f0_w2, const float* __restrict__ f0_b2,
    const float* __restrict__ phone_table, const float* __restrict__ midi_table,
    const float* __restrict__ dur_w2, const float* __restrict__ dur_b2,
    const float* __restrict__ proj_w1, const float* __restrict__ proj_b1,
    const float* __restrict__ proj_w2) {
    const int r = blockIdx.x;
    const int c = threadIdx.x;
    if (r < 100) {
        float s0 = 0.f, s1 = 0.f, s2 = 0.f, s3 = 0.f;
        #pragma unroll 8
        for (int k = 0; k < 128; k += 4) {
            s0 += phone_table[r * 128 + k + 0] * proj_w1[(64 + k + 0) * 256 + c];
            s1 += phone_table[r * 128 + k + 1] * proj_w1[(64 + k + 1) * 256 + c];
            s2 += phone_table[r * 128 + k + 2] * proj_w1[(64 + k + 2) * 256 + c];
            s3 += phone_table[r * 128 + k + 3] * proj_w1[(64 + k + 3) * 256 + c];
        }
        g_phonePh[r * 256 + c] = __float2half_rn((s0 + s1) + (s2 + s3));
    } else if (r < 228) {
        const int m = r - 100;
        float s0 = 0.f, s1 = 0.f, s2 = 0.f, s3 = 0.f;
        #pragma unroll 4
        for (int k = 0; k < 64; k += 4) {
            s0 += midi_table[m * 64 + k + 0] * proj_w1[(192 + k + 0) * 256 + c];
            s1 += midi_table[m * 64 + k + 1] * proj_w1[(192 + k + 1) * 256 + c];
            s2 += midi_table[m * 64 + k + 2] * proj_w1[(192 + k + 2) * 256 + c];
            s3 += midi_table[m * 64 + k + 3] * proj_w1[(192 + k + 3) * 256 + c];
        }
        g_midiPh[m * 256 + c] = __float2half_rn((s0 + s1) + (s2 + s3));
    } else if (r < 260) {
        const int kd = r - 228;          // derived-K 0..31 (f0 part)
        float s0 = 0.f, s1 = 0.f, s2 = 0.f, s3 = 0.f;
        #pragma unroll 4
        for (int k = 0; k < 64; k += 4) {
            s0 += f0_w2[kd * 64 + k + 0] * proj_w1[(k + 0) * 256 + c];
            s1 += f0_w2[kd * 64 + k + 1] * proj_w1[(k + 1) * 256 + c];
            s2 += f0_w2[kd * 64 + k + 2] * proj_w1[(k + 2) * 256 + c];
            s3 += f0_w2[kd * 64 + k + 3] * proj_w1[(k + 3) * 256 + c];
        }
        g_W1H[((kd >> 4) * 256 + c) * 16 + slot16(kd & 15)] =
            __float2half_rn((s0 + s1) + (s2 + s3));
    } else if (r < 292) {
        const int j = r - 260;           // dur part -> derived-K 32..63
        const int kd = 32 + j;
        float s0 = 0.f, s1 = 0.f, s2 = 0.f, s3 = 0.f;
        #pragma unroll 4
        for (int k = 0; k < 64; k += 4) {
            s0 += dur_w2[j * 64 + k + 0] * proj_w1[(256 + k + 0) * 256 + c];
            s1 += dur_w2[j * 64 + k + 1] * proj_w1[(256 + k + 1) * 256 + c];
            s2 += dur_w2[j * 64 + k + 2] * proj_w1[(256 + k + 2) * 256 + c];
            s3 += dur_w2[j * 64 + k + 3] * proj_w1[(256 + k + 3) * 256 + c];
        }
        g_W1H[((kd >> 4) * 256 + c) * 16 + slot16(kd & 15)] =
            __float2half_rn((s0 + s1) + (s2 + s3));
    } else if (r < 293) {
        float s = proj_b1[c];
        #pragma unroll 4
        for (int k = 0; k < 64; k++) {
            s += f0_b2[k] * proj_w1[k * 256 + c];
            s += dur_b2[k] * proj_w1[(256 + k) * 256 + c];
        }
        g_bias[c] = s;
    } else {
        const int k = r - 293;           // 0..255: proj_w2 input-row k, col c
        g_W2H[((k >> 4) * 256 + c) * 16 + slot16(k & 15)] =
            __float2half_rn(proj_w2[k * 256 + c]);
    }
}

// ---------------- main fused fp16-mma kernel (2 CTAs/SM, TM=64) ----------------
__global__ __launch_bounds__(256, 2)
void cond_enc_mma_kernel(
    const float* __restrict__ f0, const int* __restrict__ phone,
    const float* __restrict__ duration, const int* __restrict__ midi,
    const float* __restrict__ f0_w1, const float* __restrict__ f0_b1,
    const float* __restrict__ dur_w1, const float* __restrict__ dur_b1,
    const float* __restrict__ ln_g, const float* __restrict__ ln_b,
    const float* __restrict__ proj_b2,
    float* __restrict__ out, int npos) {
    extern __shared__ __align__(16) char smraw[];
    __half* sa1 = (__half*)smraw;                       // [64][72]
    __half* sA2 = sa1 + 64 * SA1H;                      // [64][264]
    __half* sAdd = sA2 + 64 * SA2H;                     // [64][264] bias+phone+midi
    float2* sPS = (float2*)(sAdd + 64 * SA2H);          // [64][9] partials
    float2* sMV = sPS + 64 * PS_STRIDE;                 // [64] (mu, rs)
    float* sg = (float*)(sMV + 64);                     // [256]
    float* sb = sg + 256;
    float* sb2 = sb + 256;

    const int tid = threadIdx.x;
    const int lane = tid & 31;
    const int w = tid >> 5;          // warp w owns cols [w*32, w*32+32), all 64 rows
    const int n0w = w * 32;
    const int gid = lane >> 2;
    const int q = lane & 3;
    const int base = blockIdx.x * TM;

    // ldmatrix per-lane A offsets (b16, 16-k tiles)
    const int tA = lane >> 3;
    const int aRow = (lane & 7) + (tA & 1) * 8;
    const int aKof = (tA >> 1) * 8;       // halves

    const unsigned u_sa1 = smem_u32(sa1);
    const unsigned u_sA2 = smem_u32(sA2);

    const uint2* __restrict__ W1H = (const uint2*)g_W1H;
    const uint2* __restrict__ W2H = (const uint2*)g_W2H;
    int nIdx[4];
    #pragma unroll
    for (int nt = 0; nt < 4; nt++) nIdx[nt] = n0w + nt * 8 + gid;

    sg[tid] = ln_g[tid];
    sb[tid] = ln_b[tid];
    sb2[tid] = proj_b2[tid];

    // Phase 1a: coalesced table staging. Warp w handles rows w*8..w*8+7:
    // sAdd[r][c] = fp16( g_bias[c] + phoneP[p][c] + midiP[m][c] ), 128B accesses.
    #pragma unroll 2
    for (int rr = 0; rr < 8; rr++) {
        const int r = w * 8 + rr;
        int grow = base + r; if (grow >= npos) grow = npos - 1;
        const __half2* __restrict__ pp = (const __half2*)&g_phonePh[phone[grow] * 256];
        const __half2* __restrict__ mp = (const __half2*)&g_midiPh[midi[grow] * 256];
        const float2* __restrict__ bb = (const float2*)g_bias;
        #pragma unroll
        for (int h = 0; h < 4; h++) {
            const int c2 = lane + 32 * h;        // half2 index 0..127
            const float2 a = __half22float2(pp[c2]);
            const float2 b = __half22float2(mp[c2]);
            const float2 d = bb[c2];
            *(__half2*)&sAdd[r * SA2H + c2 * 2] =
                __floats2half2_rn(d.x + a.x + b.x, d.y + a.y + b.y);
        }
    }

    // Phase 1b: tiny MLPs -> sa1 (half2 stores)
    for (int idx = tid; idx < TM * 32; idx += 256) {
        const int t = idx >> 5;
        const int u = (idx & 31) * 2;
        int row = base + t; if (row >= npos) row = npos - 1;
        float v0, v1;
        if (u < 32) {
            const float fv = f0[row];
            v0 = fv * f0_w1[u] + f0_b1[u];
            v1 = fv * f0_w1[u + 1] + f0_b1[u + 1];
        } else {
            const float dv = duration[row];
            v0 = dv * dur_w1[u - 32] + dur_b1[u - 32];
            v1 = dv * dur_w1[u - 31] + dur_b1[u - 31];
        }
        *(__half2*)&sa1[t * SA1H + u] =
            __floats2half2_rn(fmaxf(v0, 0.f), fmaxf(v1, 0.f));
    }
    __syncthreads();   // (1) sa1 + sAdd ready

    float acc[4][4][4];
    #pragma unroll
    for (int mt = 0; mt < 4; mt++)
        #pragma unroll
        for (int nt = 0; nt < 4; nt++)
            #pragma unroll
            for (int e = 0; e < 4; e++) acc[mt][nt][e] = 0.f;

    // Phase 2: GEMM1 (K=64 -> 4 fp16 k-tiles), B direct from L2
    {
        uint2 bq[2][4];
        #pragma unroll
        for (int nt = 0; nt < 4; nt++)
            bq[0][nt] = W1H[(0 * 256 + nIdx[nt]) * 4 + q];
        #pragma unroll
        for (int kt = 0; kt < 4; kt++) {
            const int cur = kt & 1, nxt = cur ^ 1;
            if (kt < 3) {
                #pragma unroll
                for (int nt = 0; nt < 4; nt++)
                    bq[nxt][nt] = W1H[((kt + 1) * 256 + nIdx[nt]) * 4 + q];
            }
            unsigned a[4][4];
            #pragma unroll
            for (int mt = 0; mt < 4; mt++)
                ldsm_x4(a[mt][0], a[mt][1], a[mt][2], a[mt][3],
                        u_sa1 + (unsigned)((mt * 16 + aRow) * SA1H +
                                           kt * 16 + aKof) * 2u);
            #pragma unroll
            for (int mt = 0; mt < 4; mt++)
                #pragma unroll
                for (int nt = 0; nt < 4; nt++)
                    mma_f16(acc[mt][nt], a[mt], (const unsigned*)&bq[cur][nt]);
        }
    }

    // Early prefetch of GEMM2's first B k-tile — hidden behind the LN phase.
    uint2 bq20[4];
    #pragma unroll
    for (int nt = 0; nt < 4; nt++)
        bq20[nt] = W2H[(0 * 256 + nIdx[nt]) * 4 + q];

    // Phase 3a: add staged (bias+phone+midi) from smem, per-row partial sums.
    {
        #pragma unroll
        for (int mt = 0; mt < 4; mt++) {
            const int r0 = mt * 16 + gid;
            const int r1 = r0 + 8;
            float s0 = 0.f, ss0 = 0.f, s1 = 0.f, ss1 = 0.f;
            #pragma unroll
            for (int nt = 0; nt < 4; nt++) {
                const int col = n0w + nt * 8 + q * 2;
                const float2 a0 = __half22float2(*(const __half2*)&sAdd[r0 * SA2H + col]);
                const float2 a1 = __half22float2(*(const __half2*)&sAdd[r1 * SA2H + col]);
                float x0 = acc[mt][nt][0] + a0.x;
                float x1 = acc[mt][nt][1] + a0.y;
                float x2 = acc[mt][nt][2] + a1.x;
                float x3 = acc[mt][nt][3] + a1.y;
                acc[mt][nt][0] = x0; acc[mt][nt][1] = x1;
                acc[mt][nt][2] = x2; acc[mt][nt][3] = x3;
                s0 += x0 + x1; ss0 += x0 * x0 + x1 * x1;
                s1 += x2 + x3; ss1 += x2 * x2 + x3 * x3;
            }
            #pragma unroll
            for (int o = 1; o < 4; o <<= 1) {
                s0 += __shfl_xor_sync(0xffffffffu, s0, o);
                ss0 += __shfl_xor_sync(0xffffffffu, ss0, o);
                s1 += __shfl_xor_sync(0xffffffffu, s1, o);
                ss1 += __shfl_xor_sync(0xffffffffu, ss1, o);
            }
            if (q == 0) {
                sPS[r0 * PS_STRIDE + w] = make_float2(s0, ss0);
                sPS[r1 * PS_STRIDE + w] = make_float2(s1, ss1);
            }
        }
    }
    __syncthreads();   // (2) partials ready

    // Phase 3b: finalize mu/rs per row (threads 0..63)
    if (tid < 64) {
        float s = 0.f, ss = 0.f;
        #pragma unroll
        for (int j = 0; j < 8; j++) {
            const float2 ps = sPS[tid * PS_STRIDE + j];
            s += ps.x; ss += ps.y;
        }
        const float mu = s * (1.f / 256.f);
        float var = ss * (1.f / 256.f) - mu * mu;
        var = fmaxf(var, 0.f);
        sMV[tid] = make_float2(mu, rsqrtf(var + EPS));
    }
    __syncthreads();   // (3) mu/rs ready

    // Phase 3c: apply LN + ReLU in-register, write half A2 tile
    {
        #pragma unroll
        for (int mt = 0; mt < 4; mt++) {
            const int r0 = mt * 16 + gid;
            const int r1 = r0 + 8;
            const float2 mv0 = sMV[r0];
            const float2 mv1 = sMV[r1];
            #pragma unroll
            for (int nt = 0; nt < 4; nt++) {
                const int col = n0w + nt * 8 + q * 2;
                const float2 gg = *(const float2*)&sg[col];
                const float2 bb = *(const float2*)&sb[col];
                float x0 = fmaxf((acc[mt][nt][0] - mv0.x) * mv0.y * gg.x + bb.x, 0.f);
                float x1 = fmaxf((acc[mt][nt][1] - mv0.x) * mv0.y * gg.y + bb.y, 0.f);
                float x2 = fmaxf((acc[mt][nt][2] - mv1.x) * mv1.y * gg.x + bb.x, 0.f);
                float x3 = fmaxf((acc[mt][nt][3] - mv1.x) * mv1.y * gg.y + bb.y, 0.f);
                *(__half2*)&sA2[r0 * SA2H + col] = __floats2half2_rn(x0, x1);
                *(__half2*)&sA2[r1 * SA2H + col] = __floats2half2_rn(x2, x3);
            }
        }
    }
    __syncthreads();   // (4) A2 ready

    #pragma unroll
    for (int mt = 0; mt < 4; mt++)
        #pragma unroll
        for (int nt = 0; nt < 4; nt++)
            #pragma unroll
            for (int e = 0; e < 4; e++) acc[mt][nt][e] = 0.f;

    // Phase 4: GEMM2 (K=256 -> 16 fp16 k-tiles), barrier-free, B from L2
    {
        uint2 bq[2][4];
        #pragma unroll
        for (int nt = 0; nt < 4; nt++)
            bq[0][nt] = bq20[nt];
        #pragma unroll 4
        for (int kt = 0; kt < 16; kt++) {
            const int cur = kt & 1, nxt = cur ^ 1;
            if (kt < 15) {
                #pragma unroll
                for (int nt = 0; nt < 4; nt++)
                    bq[nxt][nt] = W2H[((kt + 1) * 256 + nIdx[nt]) * 4 + q];
            }
            unsigned a[4][4];
            #pragma unroll
            for (int mt = 0; mt < 4; mt++)
                ldsm_x4(a[mt][0], a[mt][1], a[mt][2], a[mt][3],
                        u_sA2 + (unsigned)((mt * 16 + aRow) * SA2H +
                                           kt * 16 + aKof) * 2u);
            #pragma unroll
            for (int mt = 0; mt < 4; mt++)
                #pragma unroll
                for (int nt = 0; nt < 4; nt++)
                    mma_f16(acc[mt][nt], a[mt], (const unsigned*)&bq[cur][nt]);
        }
    }

    // Phase 5: write output (+proj_b2)
    #pragma unroll
    for (int mt = 0; mt < 4; mt++) {
        const int row = mt * 16 + gid;
        #pragma unroll
        for (int nt = 0; nt < 4; nt++) {
            const int col = n0w + nt * 8 + q * 2;
            const float b2a = sb2[col];
            const float b2b = sb2[col + 1];
            if (base + row < npos)
                *(float2*)&out[(size_t)(base + row) * 256 + col] =
                    make_float2(acc[mt][nt][0] + b2a, acc[mt][nt][1] + b2b);
            if (base + row + 8 < npos)
                *(float2*)&out[(size_t)(base + row + 8) * 256 + col] =
                    make_float2(acc[mt][nt][2] + b2a, acc[mt][nt][3] + b2b);
        }
    }
}

extern "C" void kernel_launch(void* const* d_in, const int* in_sizes, int n_in,
                              void* d_out, int out_size) {
    const float* f0          = (const float*)d_in[0];
    const int*   phone       = (const int*)  d_in[1];
    const float* duration    = (const float*)d_in[2];
    const int*   midi        = (const int*)  d_in[3];
    const float* f0_w1       = (const float*)d_in[4];
    const float* f0_b1       = (const float*)d_in[5];
    const float* f0_w2       = (const float*)d_in[6];
    const float* f0_b2       = (const float*)d_in[7];
    const float* phone_table = (const float*)d_in[8];
    const float* midi_table  = (const float*)d_in[9];
    const float* dur_w1      = (const float*)d_in[10];
    const float* dur_b1      = (const float*)d_in[11];
    const float* dur_w2      = (const float*)d_in[12];
    const float* dur_b2      = (const float*)d_in[13];
    const float* proj_w1     = (const float*)d_in[14];
    const float* proj_b1     = (const float*)d_in[15];
    const float* ln_g        = (const float*)d_in[16];
    const float* ln_b        = (const float*)d_in[17];
    const float* proj_w2     = (const float*)d_in[18];
    const float* proj_b2     = (const float*)d_in[19];
    float* out = (float*)d_out;
    const int npos = in_sizes[0];

    precompute_kernel<<<549, 256>>>(f0_w2, f0_b2, phone_table, midi_table,
                                    dur_w2, dur_b2, proj_w1, proj_b1, proj_w2);

    const size_t smem_bytes =
        (size_t)(64 * SA1H + 64 * SA2H * 2) * sizeof(__half) +
        (size_t)(64 * PS_STRIDE + 64) * sizeof(float2) +
        (size_t)(3 * 256) * sizeof(float) + 64;
    cudaFuncSetAttribute(cond_enc_mma_kernel,
                         cudaFuncAttributeMaxDynamicSharedMemorySize,
                         (int)smem_bytes);
    const int grid = (npos + TM - 1) / TM;
    cond_enc_mma_kernel<<<grid, 256, smem_bytes>>>(
        f0, phone, duration, midi, f0_w1, f0_b1, dur_w1, dur_b1,
        ln_g, ln_b, proj_b2, out, npos);
}

// round 12
// speedup vs baseline: 1.1216x; 1.0041x over previous
#include <cuda_runtime.h>
#include <cuda_fp16.h>

#define TM 32
#define EPS 1e-5f

#define SA1H 72    // [32][72] halves: row step 144B == 16B mod 128B (LDSM-clean)
#define SA2H 264   // [32][264] halves: row step 528B == 16B mod 128B
#define PS_STRIDE 9

// ---------------- device scratch ----------------
__device__ __align__(16) __half g_phonePh[100 * 256];   // fp16 folded phone table
__device__ __align__(16) __half g_midiPh[128 * 256];    // fp16 folded midi table
__device__ __align__(16) float g_bias[256];
// fp16 fragment-packed B: [kt16][n=256][16 halves]; lane q reads halves
// [q*4 .. q*4+3] = k elements {2q, 2q+1, 2q+8, 2q+9} of that 16-k tile (one 8B read).
__device__ __align__(16) __half g_W1H[4 * 256 * 16];    // K=64  -> 4 k-tiles
__device__ __align__(16) __half g_W2H[16 * 256 * 16];   // K=256 -> 16 k-tiles

__host__ __device__ __forceinline__ int slot16(int kk) {
    return ((kk & 7) >> 1) * 4 + ((kk >> 3) & 1) * 2 + (kk & 1);
}

__device__ __forceinline__ unsigned smem_u32(const void* p) {
    unsigned a;
    asm("{ .reg .u64 t; cvta.to.shared.u64 t, %1; cvt.u32.u64 %0, t; }"
        : "=r"(a) : "l"(p));
    return a;
}

__device__ __forceinline__ void ldsm_x4(unsigned& r0, unsigned& r1,
                                        unsigned& r2, unsigned& r3,
                                        unsigned addr) {
    asm volatile("ldmatrix.sync.aligned.m8n8.x4.shared.b16 {%0,%1,%2,%3}, [%4];"
                 : "=r"(r0), "=r"(r1), "=r"(r2), "=r"(r3) : "r"(addr));
}

__device__ __forceinline__ void mma_f16(float* c, const unsigned* a,
                                        const unsigned* b) {
    asm volatile(
        "mma.sync.aligned.m16n8k16.row.col.f32.f16.f16.f32 "
        "{%0,%1,%2,%3}, {%4,%5,%6,%7}, {%8,%9}, {%0,%1,%2,%3};"
        : "+f"(c[0]), "+f"(c[1]), "+f"(c[2]), "+f"(c[3])
        : "r"(a[0]), "r"(a[1]), "r"(a[2]), "r"(a[3]), "r"(b[0]), "r"(b[1]));
}

// ---------------- precompute (4 independent accumulators: short dep chains) ----
__global__ void precompute_kernel(
    const float* __restrict__ f0_w2, const float* __restrict__ f0_b2,
    const float* __restrict__ phone_table, const float* __restrict__ midi_table,
    const float* __restrict__ dur_w2, const float* __restrict__ dur_b2,
    const float* __restrict__ proj_w1, const float* __restrict__ proj_b1,
    const float* __restrict__ proj_w2) {
    const int r = blockIdx.x;
    const int c = threadIdx.x;
    if (r < 100) {
        float s0 = 0.f, s1 = 0.f, s2 = 0.f, s3 = 0.f;
        #pragma unroll 8
        for (int k = 0; k < 128; k += 4) {
            s0 += phone_table[r * 128 + k + 0] * proj_w1[(64 + k + 0) * 256 + c];
            s1 += phone_table[r * 128 + k + 1] * proj_w1[(64 + k + 1) * 256 + c];
            s2 += phone_table[r * 128 + k + 2] * proj_w1[(64 + k + 2) * 256 + c];
            s3 += phone_table[r * 128 + k + 3] * proj_w1[(64 + k + 3) * 256 + c];
        }
        g_phonePh[r * 256 + c] = __float2half_rn((s0 + s1) + (s2 + s3));
    } else if (r < 228) {
        const int m = r - 100;
        float s0 = 0.f, s1 = 0.f, s2 = 0.f, s3 = 0.f;
        #pragma unroll 4
        for (int k = 0; k < 64; k += 4) {
            s0 += midi_table[m * 64 + k + 0] * proj_w1[(192 + k + 0) * 256 + c];
            s1 += midi_table[m * 64 + k + 1] * proj_w1[(192 + k + 1) * 256 + c];
            s2 += midi_table[m * 64 + k + 2] * proj_w1[(192 + k + 2) * 256 + c];
            s3 += midi_table[m * 64 + k + 3] * proj_w1[(192 + k + 3) * 256 + c];
        }
        g_midiPh[m * 256 + c] = __float2half_rn((s0 + s1) + (s2 + s3));
    } else if (r < 260) {
        const int kd = r - 228;          // derived-K 0..31 (f0 part)
        float s0 = 0.f, s1 = 0.f, s2 = 0.f, s3 = 0.f;
        #pragma unroll 4
        for (int k = 0; k < 64; k += 4) {
            s0 += f0_w2[kd * 64 + k + 0] * proj_w1[(k + 0) * 256 + c];
            s1 += f0_w2[kd * 64 + k + 1] * proj_w1[(k + 1) * 256 + c];
            s2 += f0_w2[kd * 64 + k + 2] * proj_w1[(k + 2) * 256 + c];
            s3 += f0_w2[kd * 64 + k + 3] * proj_w1[(k + 3) * 256 + c];
        }
        g_W1H[((kd >> 4) * 256 + c) * 16 + slot16(kd & 15)] =
            __float2half_rn((s0 + s1) + (s2 + s3));
    } else if (r < 292) {
        const int j = r - 260;           // dur part -> derived-K 32..63
        const int kd = 32 + j;
        float s0 = 0.f, s1 = 0.f, s2 = 0.f, s3 = 0.f;
        #pragma unroll 4
        for (int k = 0; k < 64; k += 4) {
            s0 += dur_w2[j * 64 + k + 0] * proj_w1[(256 + k + 0) * 256 + c];
            s1 += dur_w2[j * 64 + k + 1] * proj_w1[(256 + k + 1) * 256 + c];
            s2 += dur_w2[j * 64 + k + 2] * proj_w1[(256 + k + 2) * 256 + c];
            s3 += dur_w2[j * 64 + k + 3] * proj_w1[(256 + k + 3) * 256 + c];
        }
        g_W1H[((kd >> 4) * 256 + c) * 16 + slot16(kd & 15)] =
            __float2half_rn((s0 + s1) + (s2 + s3));
    } else if (r < 293) {
        float s = proj_b1[c];
        #pragma unroll 4
        for (int k = 0; k < 64; k++) {
            s += f0_b2[k] * proj_w1[k * 256 + c];
            s += dur_b2[k] * proj_w1[(256 + k) * 256 + c];
        }
        g_bias[c] = s;
    } else {
        const int k = r - 293;           // 0..255: proj_w2 input-row k, col c
        g_W2H[((k >> 4) * 256 + c) * 16 + slot16(k & 15)] =
            __float2half_rn(proj_w2[k * 256 + c]);
    }
}

// ---------------- main fused fp16-mma kernel (3 CTAs/SM, TM=32, sAdd staged) ----
__global__ __launch_bounds__(256, 3)
void cond_enc_mma_kernel(
    const float* __restrict__ f0, const int* __restrict__ phone,
    const float* __restrict__ duration, const int* __restrict__ midi,
    const float* __restrict__ f0_w1, const float* __restrict__ f0_b1,
    const float* __restrict__ dur_w1, const float* __restrict__ dur_b1,
    const float* __restrict__ ln_g, const float* __restrict__ ln_b,
    const float* __restrict__ proj_b2,
    float* __restrict__ out, int npos) {
    extern __shared__ __align__(16) char smraw[];
    __half* sa1 = (__half*)smraw;                       // [32][72]
    __half* sA2 = sa1 + 32 * SA1H;                      // [32][264]
    __half* sAdd = sA2 + 32 * SA2H;                     // [32][264] bias+phone+midi
    float2* sPS = (float2*)(sAdd + 32 * SA2H);          // [32][9] partials
    float2* sMV = sPS + 32 * PS_STRIDE;                 // [32] (mu, rs)
    float* sg = (float*)(sMV + 32);                     // [256]
    float* sb = sg + 256;
    float* sb2 = sb + 256;

    const int tid = threadIdx.x;
    const int lane = tid & 31;
    const int w = tid >> 5;          // warp w owns cols [w*32, w*32+32), all 32 rows
    const int n0w = w * 32;
    const int gid = lane >> 2;
    const int q = lane & 3;
    const int base = blockIdx.x * TM;

    // ldmatrix per-lane A offsets (b16, 16-k tiles)
    const int tA = lane >> 3;
    const int aRow = (lane & 7) + (tA & 1) * 8;
    const int aKof = (tA >> 1) * 8;       // halves

    const unsigned u_sa1 = smem_u32(sa1);
    const unsigned u_sA2 = smem_u32(sA2);

    const uint2* __restrict__ W1H = (const uint2*)g_W1H;
    const uint2* __restrict__ W2H = (const uint2*)g_W2H;
    int nIdx[4];
    #pragma unroll
    for (int nt = 0; nt < 4; nt++) nIdx[nt] = n0w + nt * 8 + gid;

    sg[tid] = ln_g[tid];
    sb[tid] = ln_b[tid];
    sb2[tid] = proj_b2[tid];

    // Phase 1a: coalesced table staging. Warp w handles rows w*4..w*4+3:
    // sAdd[r][c] = fp16( g_bias[c] + phoneP[p][c] + midiP[m][c] ), 128B accesses.
    #pragma unroll
    for (int rr = 0; rr < 4; rr++) {
        const int r = w * 4 + rr;
        int grow = base + r; if (grow >= npos) grow = npos - 1;
        const __half2* __restrict__ pp = (const __half2*)&g_phonePh[phone[grow] * 256];
        const __half2* __restrict__ mp = (const __half2*)&g_midiPh[midi[grow] * 256];
        const float2* __restrict__ bb = (const float2*)g_bias;
        #pragma unroll
        for (int h = 0; h < 4; h++) {
            const int c2 = lane + 32 * h;        // half2 index 0..127
            const float2 a = __half22float2(pp[c2]);
            const float2 b = __half22float2(mp[c2]);
            const float2 d = bb[c2];
            *(__half2*)&sAdd[r * SA2H + c2 * 2] =
                __floats2half2_rn(d.x + a.x + b.x, d.y + a.y + b.y);
        }
    }

    // Phase 1b: tiny MLPs -> sa1 (half2 stores)
    for (int idx = tid; idx < TM * 32; idx += 256) {
        const int t = idx >> 5;
        const int u = (idx & 31) * 2;
        int row = base + t; if (row >= npos) row = npos - 1;
        float v0, v1;
        if (u < 32) {
            const float fv = f0[row];
            v0 = fv * f0_w1[u] + f0_b1[u];
            v1 = fv * f0_w1[u + 1] + f0_b1[u + 1];
        } else {
            const float dv = duration[row];
            v0 = dv * dur_w1[u - 32] + dur_b1[u - 32];
            v1 = dv * dur_w1[u - 31] + dur_b1[u - 31];
        }
        *(__half2*)&sa1[t * SA1H + u] =
            __floats2half2_rn(fmaxf(v0, 0.f), fmaxf(v1, 0.f));
    }
    __syncthreads();   // (1) sa1 + sAdd ready

    float acc[2][4][4];
    #pragma unroll
    for (int mt = 0; mt < 2; mt++)
        #pragma unroll
        for (int nt = 0; nt < 4; nt++)
            #pragma unroll
            for (int e = 0; e < 4; e++) acc[mt][nt][e] = 0.f;

    // Phase 2: GEMM1 (K=64 -> 4 fp16 k-tiles), B direct from L2
    {
        uint2 bq[2][4];
        #pragma unroll
        for (int nt = 0; nt < 4; nt++)
            bq[0][nt] = W1H[(0 * 256 + nIdx[nt]) * 4 + q];
        #pragma unroll
        for (int kt = 0; kt < 4; kt++) {
            const int cur = kt & 1, nxt = cur ^ 1;
            if (kt < 3) {
                #pragma unroll
                for (int nt = 0; nt < 4; nt++)
                    bq[nxt][nt] = W1H[((kt + 1) * 256 + nIdx[nt]) * 4 + q];
            }
            unsigned a[2][4];
            #pragma unroll
            for (int mt = 0; mt < 2; mt++)
                ldsm_x4(a[mt][0], a[mt][1], a[mt][2], a[mt][3],
                        u_sa1 + (unsigned)((mt * 16 + aRow) * SA1H +
                                           kt * 16 + aKof) * 2u);
            #pragma unroll
            for (int mt = 0; mt < 2; mt++)
                #pragma unroll
                for (int nt = 0; nt < 4; nt++)
                    mma_f16(acc[mt][nt], a[mt], (const unsigned*)&bq[cur][nt]);
        }
    }

    // Phase 3a: add staged (bias+phone+midi) from smem, per-row partial sums.
    {
        #pragma unroll
        for (int mt = 0; mt < 2; mt++) {
            const int r0 = mt * 16 + gid;
            const int r1 = r0 + 8;
            float s0 = 0.f, ss0 = 0.f, s1 = 0.f, ss1 = 0.f;
            #pragma unroll
            for (int nt = 0; nt < 4; nt++) {
                const int col = n0w + nt * 8 + q * 2;
                const float2 a0 = __half22float2(*(const __half2*)&sAdd[r0 * SA2H + col]);
                const float2 a1 = __half22float2(*(const __half2*)&sAdd[r1 * SA2H + col]);
                float x0 = acc[mt][nt][0] + a0.x;
                float x1 = acc[mt][nt][1] + a0.y;
                float x2 = acc[mt][nt][2] + a1.x;
                float x3 = acc[mt][nt][3] + a1.y;
                acc[mt][nt][0] = x0; acc[mt][nt][1] = x1;
                acc[mt][nt][2] = x2; acc[mt][nt][3] = x3;
                s0 += x0 + x1; ss0 += x0 * x0 + x1 * x1;
                s1 += x2 + x3; ss1 += x2 * x2 + x3 * x3;
            }
            #pragma unroll
            for (int o = 1; o < 4; o <<= 1) {
                s0 += __shfl_xor_sync(0xffffffffu, s0, o);
                ss0 += __shfl_xor_sync(0xffffffffu, ss0, o);
                s1 += __shfl_xor_sync(0xffffffffu, s1, o);
                ss1 += __shfl_xor_sync(0xffffffffu, ss1, o);
            }
            if (q == 0) {
                sPS[r0 * PS_STRIDE + w] = make_float2(s0, ss0);
                sPS[r1 * PS_STRIDE + w] = make_float2(s1, ss1);
            }
        }
    }
    __syncthreads();   // (2) partials ready

    // Phase 3b: finalize mu/rs per row (threads 0..31)
    if (tid < 32) {
        float s = 0.f, ss = 0.f;
        #pragma unroll
        for (int j = 0; j < 8; j++) {
            const float2 ps = sPS[tid * PS_STRIDE + j];
            s += ps.x; ss += ps.y;
        }
        const float mu = s * (1.f / 256.f);
        float var = ss * (1.f / 256.f) - mu * mu;
        var = fmaxf(var, 0.f);
        sMV[tid] = make_float2(mu, rsqrtf(var + EPS));
    }
    __syncthreads();   // (3) mu/rs ready

    // Phase 3c: apply LN + ReLU in-register, write half A2 tile
    {
        #pragma unroll
        for (int mt = 0; mt < 2; mt++) {
            const int r0 = mt * 16 + gid;
            const int r1 = r0 + 8;
            const float2 mv0 = sMV[r0];
            const float2 mv1 = sMV[r1];
            #pragma unroll
            for (int nt = 0; nt < 4; nt++) {
                const int col = n0w + nt * 8 + q * 2;
                const float2 gg = *(const float2*)&sg[col];
                const float2 bb = *(const float2*)&sb[col];
                float x0 = fmaxf((acc[mt][nt][0] - mv0.x) * mv0.y * gg.x + bb.x, 0.f);
                float x1 = fmaxf((acc[mt][nt][1] - mv0.x) * mv0.y * gg.y + bb.y, 0.f);
                float x2 = fmaxf((acc[mt][nt][2] - mv1.x) * mv1.y * gg.x + bb.x, 0.f);
                float x3 = fmaxf((acc[mt][nt][3] - mv1.x) * mv1.y * gg.y + bb.y, 0.f);
                *(__half2*)&sA2[r0 * SA2H + col] = __floats2half2_rn(x0, x1);
                *(__half2*)&sA2[r1 * SA2H + col] = __floats2half2_rn(x2, x3);
            }
        }
    }
    __syncthreads();   // (4) A2 ready

    #pragma unroll
    for (int mt = 0; mt < 2; mt++)
        #pragma unroll
        for (int nt = 0; nt < 4; nt++)
            #pragma unroll
            for (int e = 0; e < 4; e++) acc[mt][nt][e] = 0.f;

    // Phase 4: GEMM2 (K=256 -> 16 fp16 k-tiles), barrier-free, B from L2
    {
        uint2 bq[2][4];
        #pragma unroll
        for (int nt = 0; nt < 4; nt++)
            bq[0][nt] = W2H[(0 * 256 + nIdx[nt]) * 4 + q];
        #pragma unroll 4
        for (int kt = 0; kt < 16; kt++) {
            const int cur = kt & 1, nxt = cur ^ 1;
            if (kt < 15) {
                #pragma unroll
                for (int nt = 0; nt < 4; nt++)
                    bq[nxt][nt] = W2H[((kt + 1) * 256 + nIdx[nt]) * 4 + q];
            }
            unsigned a[2][4];
            #pragma unroll
            for (int mt = 0; mt < 2; mt++)
                ldsm_x4(a[mt][0], a[mt][1], a[mt][2], a[mt][3],
                        u_sA2 + (unsigned)((mt * 16 + aRow) * SA2H +
                                           kt * 16 + aKof) * 2u);
            #pragma unroll
            for (int mt = 0; mt < 2; mt++)
                #pragma unroll
                for (int nt = 0; nt < 4; nt++)
                    mma_f16(acc[mt][nt], a[mt], (const unsigned*)&bq[cur][nt]);
        }
    }

    // Phase 5: write output (+proj_b2)
    #pragma unroll
    for (int mt = 0; mt < 2; mt++) {
        const int row = mt * 16 + gid;
        #pragma unroll
        for (int nt = 0; nt < 4; nt++) {
            const int col = n0w + nt * 8 + q * 2;
            const float b2a = sb2[col];
            const float b2b = sb2[col + 1];
            if (base + row < npos)
                *(float2*)&out[(size_t)(base + row) * 256 + col] =
                    make_float2(acc[mt][nt][0] + b2a, acc[mt][nt][1] + b2b);
            if (base + row + 8 < npos)
                *(float2*)&out[(size_t)(base + row + 8) * 256 + col] =
                    make_float2(acc[mt][nt][2] + b2a, acc[mt][nt][3] + b2b);
        }
    }
}

extern "C" void kernel_launch(void* const* d_in, const int* in_sizes, int n_in,
                              void* d_out, int out_size) {
    const float* f0          = (const float*)d_in[0];
    const int*   phone       = (const int*)  d_in[1];
    const float* duration    = (const float*)d_in[2];
    const int*   midi        = (const int*)  d_in[3];
    const float* f0_w1       = (const float*)d_in[4];
    const float* f0_b1       = (const float*)d_in[5];
    const float* f0_w2       = (const float*)d_in[6];
    const float* f0_b2       = (const float*)d_in[7];
    const float* phone_table = (const float*)d_in[8];
    const float* midi_table  = (const float*)d_in[9];
    const float* dur_w1      = (const float*)d_in[10];
    const float* dur_b1      = (const float*)d_in[11];
    const float* dur_w2      = (const float*)d_in[12];
    const float* dur_b2      = (const float*)d_in[13];
    const float* proj_w1     = (const float*)d_in[14];
    const float* proj_b1     = (const float*)d_in[15];
    const float* ln_g        = (const float*)d_in[16];
    const float* ln_b        = (const float*)d_in[17];
    const float* proj_w2     = (const float*)d_in[18];
    const float* proj_b2     = (const float*)d_in[19];
    float* out = (float*)d_out;
    const int npos = in_sizes[0];

    precompute_kernel<<<549, 256>>>(f0_w2, f0_b2, phone_table, midi_table,
                                    dur_w2, dur_b2, proj_w1, proj_b1, proj_w2);

    const size_t smem_bytes =
        (size_t)(32 * SA1H + 32 * SA2H * 2) * sizeof(__half) +
        (size_t)(32 * PS_STRIDE + 32) * sizeof(float2) +
        (size_t)(3 * 256) * sizeof(float) + 64;
    cudaFuncSetAttribute(cond_enc_mma_kernel,
                         cudaFuncAttributeMaxDynamicSharedMemorySize,
                         (int)smem_bytes);
    const int grid = (npos + TM - 1) / TM;
    cond_enc_mma_kernel<<<grid, 256, smem_bytes>>>(
        f0, phone, duration, midi, f0_w1, f0_b1, dur_w1, dur_b1,
        ln_g, ln_b, proj_b2, out, npos);
}

// round 13
// speedup vs baseline: 1.1385x; 1.0151x over previous
#include <cuda_runtime.h>
#include <cuda_fp16.h>

#define TM 64
#define EPS 1e-5f

#define SA1H 72    // [64][72] halves: row step 144B == 16B mod 128B (LDSM-clean)
#define SA2H 264   // [64][264] halves: row step 528B == 16B mod 128B
#define PS_STRIDE 9

// ---------------- device scratch ----------------
__device__ __align__(16) __half g_phonePh[100 * 256];   // fp16 folded phone table
__device__ __align__(16) __half g_midiPh[128 * 256];    // fp16 folded midi table
__device__ __align__(16) float g_bias[256];
// fp16 fragment-packed B: [kt16][n=256][16 halves]; lane q reads halves
// [q*4 .. q*4+3] = k elements {2q, 2q+1, 2q+8, 2q+9} of that 16-k tile (one 8B read).
__device__ __align__(16) __half g_W1H[4 * 256 * 16];    // K=64  -> 4 k-tiles
__device__ __align__(16) __half g_W2H[16 * 256 * 16];   // K=256 -> 16 k-tiles

__host__ __device__ __forceinline__ int slot16(int kk) {
    return ((kk & 7) >> 1) * 4 + ((kk >> 3) & 1) * 2 + (kk & 1);
}

__device__ __forceinline__ unsigned smem_u32(const void* p) {
    unsigned a;
    asm("{ .reg .u64 t; cvta.to.shared.u64 t, %1; cvt.u32.u64 %0, t; }"
        : "=r"(a) : "l"(p));
    return a;
}

__device__ __forceinline__ void ldsm_x4(unsigned& r0, unsigned& r1,
                                        unsigned& r2, unsigned& r3,
                                        unsigned addr) {
    asm volatile("ldmatrix.sync.aligned.m8n8.x4.shared.b16 {%0,%1,%2,%3}, [%4];"
                 : "=r"(r0), "=r"(r1), "=r"(r2), "=r"(r3) : "r"(addr));
}

__device__ __forceinline__ void mma_f16(float* c, const unsigned* a,
                                        const unsigned* b) {
    asm volatile(
        "mma.sync.aligned.m16n8k16.row.col.f32.f16.f16.f32 "
        "{%0,%1,%2,%3}, {%4,%5,%6,%7}, {%8,%9}, {%0,%1,%2,%3};"
        : "+f"(c[0]), "+f"(c[1]), "+f"(c[2]), "+f"(c[3])
        : "r"(a[0]), "r"(a[1]), "r"(a[2]), "r"(a[3]), "r"(b[0]), "r"(b[1]));
}

// ---------------- precompute (4 independent accumulators: short dep chains) ----
__global__ void precompute_kernel(
    const float* __restrict__ f0_w2, const float* __restrict__ f0_b2,
    const float* __restrict__ phone_table, const float* __restrict__ midi_table,
    const float* __restrict__ dur_w2, const float* __restrict__ dur_b2,
    const float* __restrict__ proj_w1, const float* __restrict__ proj_b1,
    const float* __restrict__ proj_w2) {
    const int r = blockIdx.x;
    const int c = threadIdx.x;
    if (r < 100) {
        float s0 = 0.f, s1 = 0.f, s2 = 0.f, s3 = 0.f;
        #pragma unroll 8
        for (int k = 0; k < 128; k += 4) {
            s0 += phone_table[r * 128 + k + 0] * proj_w1[(64 + k + 0) * 256 + c];
            s1 += phone_table[r * 128 + k + 1] * proj_w1[(64 + k + 1) * 256 + c];
            s2 += phone_table[r * 128 + k + 2] * proj_w1[(64 + k + 2) * 256 + c];
            s3 += phone_table[r * 128 + k + 3] * proj_w1[(64 + k + 3) * 256 + c];
        }
        g_phonePh[r * 256 + c] = __float2half_rn((s0 + s1) + (s2 + s3));
    } else if (r < 228) {
        const int m = r - 100;
        float s0 = 0.f, s1 = 0.f, s2 = 0.f, s3 = 0.f;
        #pragma unroll 4
        for (int k = 0; k < 64; k += 4) {
            s0 += midi_table[m * 64 + k + 0] * proj_w1[(192 + k + 0) * 256 + c];
            s1 += midi_table[m * 64 + k + 1] * proj_w1[(192 + k + 1) * 256 + c];
            s2 += midi_table[m * 64 + k + 2] * proj_w1[(192 + k + 2) * 256 + c];
            s3 += midi_table[m * 64 + k + 3] * proj_w1[(192 + k + 3) * 256 + c];
        }
        g_midiPh[m * 256 + c] = __float2half_rn((s0 + s1) + (s2 + s3));
    } else if (r < 260) {
        const int kd = r - 228;          // derived-K 0..31 (f0 part)
        float s0 = 0.f, s1 = 0.f, s2 = 0.f, s3 = 0.f;
        #pragma unroll 4
        for (int k = 0; k < 64; k += 4) {
            s0 += f0_w2[kd * 64 + k + 0] * proj_w1[(k + 0) * 256 + c];
            s1 += f0_w2[kd * 64 + k + 1] * proj_w1[(k + 1) * 256 + c];
            s2 += f0_w2[kd * 64 + k + 2] * proj_w1[(k + 2) * 256 + c];
            s3 += f0_w2[kd * 64 + k + 3] * proj_w1[(k + 3) * 256 + c];
        }
        g_W1H[((kd >> 4) * 256 + c) * 16 + slot16(kd & 15)] =
            __float2half_rn((s0 + s1) + (s2 + s3));
    } else if (r < 292) {
        const int j = r - 260;           // dur part -> derived-K 32..63
        const int kd = 32 + j;
        float s0 = 0.f, s1 = 0.f, s2 = 0.f, s3 = 0.f;
        #pragma unroll 4
        for (int k = 0; k < 64; k += 4) {
            s0 += dur_w2[j * 64 + k + 0] * proj_w1[(256 + k + 0) * 256 + c];
            s1 += dur_w2[j * 64 + k + 1] * proj_w1[(256 + k + 1) * 256 + c];
            s2 += dur_w2[j * 64 + k + 2] * proj_w1[(256 + k + 2) * 256 + c];
            s3 += dur_w2[j * 64 + k + 3] * proj_w1[(256 + k + 3) * 256 + c];
        }
        g_W1H[((kd >> 4) * 256 + c) * 16 + slot16(kd & 15)] =
            __float2half_rn((s0 + s1) + (s2 + s3));
    } else if (r < 293) {
        float s = proj_b1[c];
        #pragma unroll 4
        for (int k = 0; k < 64; k++) {
            s += f0_b2[k] * proj_w1[k * 256 + c];
            s += dur_b2[k] * proj_w1[(256 + k) * 256 + c];
        }
        g_bias[c] = s;
    } else {
        const int k = r - 293;           // 0..255: proj_w2 input-row k, col c
        g_W2H[((k >> 4) * 256 + c) * 16 + slot16(k & 15)] =
            __float2half_rn(proj_w2[k * 256 + c]);
    }
}

// ---------------- main fused fp16-mma kernel (2 CTAs/SM, TM=64) ----------------
__global__ __launch_bounds__(256, 2)
void cond_enc_mma_kernel(
    const float* __restrict__ f0, const int* __restrict__ phone,
    const float* __restrict__ duration, const int* __restrict__ midi,
    const float* __restrict__ f0_w1, const float* __restrict__ f0_b1,
    const float* __restrict__ dur_w1, const float* __restrict__ dur_b1,
    const float* __restrict__ ln_g, const float* __restrict__ ln_b,
    const float* __restrict__ proj_b2,
    float* __restrict__ out, int npos) {
    extern __shared__ __align__(16) char smraw[];
    __half* sa1 = (__half*)smraw;                       // [64][72]
    __half* sA2 = sa1 + 64 * SA1H;                      // [64][264]
    __half* sAdd = sA2 + 64 * SA2H;                     // [64][264] bias+phone+midi
    float2* sPS = (float2*)(sAdd + 64 * SA2H);          // [64][9] partials
    float2* sMV = sPS + 64 * PS_STRIDE;                 // [64] (mu, rs)
    float* sg = (float*)(sMV + 64);                     // [256]
    float* sb = sg + 256;
    float* sb2 = sb + 256;

    const int tid = threadIdx.x;
    const int lane = tid & 31;
    const int w = tid >> 5;          // warp w owns cols [w*32, w*32+32), all 64 rows
    const int n0w = w * 32;
    const int gid = lane >> 2;
    const int q = lane & 3;
    const int base = blockIdx.x * TM;

    // ldmatrix per-lane A offsets (b16, 16-k tiles)
    const int tA = lane >> 3;
    const int aRow = (lane & 7) + (tA & 1) * 8;
    const int aKof = (tA >> 1) * 8;       // halves

    const unsigned u_sa1 = smem_u32(sa1);
    const unsigned u_sA2 = smem_u32(sA2);

    // Hoisted byte offsets: B fragment for (kt, nt) lives at
    //   g_W*H + bOff[nt] + kt*8192   (bytes);  bOff = (n*16 + q*4)*2
    unsigned bOff[4];
    #pragma unroll
    for (int nt = 0; nt < 4; nt++)
        bOff[nt] = (unsigned)(((n0w + nt * 8 + gid) * 16 + q * 4) * 2);
    const char* __restrict__ W1B = (const char*)g_W1H;
    const char* __restrict__ W2B = (const char*)g_W2H;

    // Hoisted LDSM base addresses (byte): addr = aBase*[mt] + kt*32
    unsigned aBase1[4], aBase2[4];
    #pragma unroll
    for (int mt = 0; mt < 4; mt++) {
        aBase1[mt] = u_sa1 + (unsigned)(((mt * 16 + aRow) * SA1H + aKof) * 2);
        aBase2[mt] = u_sA2 + (unsigned)(((mt * 16 + aRow) * SA2H + aKof) * 2);
    }

    sg[tid] = ln_g[tid];
    sb[tid] = ln_b[tid];
    sb2[tid] = proj_b2[tid];

    // Phase 1a: coalesced table staging. Warp w handles rows w*8..w*8+7:
    // sAdd[r][c] = fp16( g_bias[c] + phoneP[p][c] + midiP[m][c] ), 128B accesses.
    #pragma unroll 2
    for (int rr = 0; rr < 8; rr++) {
        const int r = w * 8 + rr;
        int grow = base + r; if (grow >= npos) grow = npos - 1;
        const __half2* __restrict__ pp = (const __half2*)&g_phonePh[phone[grow] * 256];
        const __half2* __restrict__ mp = (const __half2*)&g_midiPh[midi[grow] * 256];
        const float2* __restrict__ bb = (const float2*)g_bias;
        #pragma unroll
        for (int h = 0; h < 4; h++) {
            const int c2 = lane + 32 * h;        // half2 index 0..127
            const float2 a = __half22float2(pp[c2]);
            const float2 b = __half22float2(mp[c2]);
            const float2 d = bb[c2];
            *(__half2*)&sAdd[r * SA2H + c2 * 2] =
                __floats2half2_rn(d.x + a.x + b.x, d.y + a.y + b.y);
        }
    }

    // Phase 1b: tiny MLPs -> sa1 (half2 stores)
    for (int idx = tid; idx < TM * 32; idx += 256) {
        const int t = idx >> 5;
        const int u = (idx & 31) * 2;
        int row = base + t; if (row >= npos) row = npos - 1;
        float v0, v1;
        if (u < 32) {
            const float fv = f0[row];
            v0 = fv * f0_w1[u] + f0_b1[u];
            v1 = fv * f0_w1[u + 1] + f0_b1[u + 1];
        } else {
            const float dv = duration[row];
            v0 = dv * dur_w1[u - 32] + dur_b1[u - 32];
            v1 = dv * dur_w1[u - 31] + dur_b1[u - 31];
        }
        *(__half2*)&sa1[t * SA1H + u] =
            __floats2half2_rn(fmaxf(v0, 0.f), fmaxf(v1, 0.f));
    }
    __syncthreads();   // (1) sa1 + sAdd ready

    float acc[4][4][4];
    #pragma unroll
    for (int mt = 0; mt < 4; mt++)
        #pragma unroll
        for (int nt = 0; nt < 4; nt++)
            #pragma unroll
            for (int e = 0; e < 4; e++) acc[mt][nt][e] = 0.f;

    // Phase 2: GEMM1 (K=64 -> 4 fp16 k-tiles), B direct from L2, imm addressing
    {
        uint2 bq[2][4];
        #pragma unroll
        for (int nt = 0; nt < 4; nt++)
            bq[0][nt] = *(const uint2*)(W1B + bOff[nt]);
        #pragma unroll
        for (int kt = 0; kt < 4; kt++) {
            const int cur = kt & 1, nxt = cur ^ 1;
            if (kt < 3) {
                #pragma unroll
                for (int nt = 0; nt < 4; nt++)
                    bq[nxt][nt] = *(const uint2*)(W1B + bOff[nt] + (kt + 1) * 8192);
            }
            unsigned a[4][4];
            #pragma unroll
            for (int mt = 0; mt < 4; mt++)
                ldsm_x4(a[mt][0], a[mt][1], a[mt][2], a[mt][3],
                        aBase1[mt] + (unsigned)(kt * 32));
            #pragma unroll
            for (int mt = 0; mt < 4; mt++)
                #pragma unroll
                for (int nt = 0; nt < 4; nt++)
                    mma_f16(acc[mt][nt], a[mt], (const unsigned*)&bq[cur][nt]);
        }
    }

    // Early prefetch of GEMM2's first B k-tile — hidden behind the LN phase.
    uint2 bq20[4];
    #pragma unroll
    for (int nt = 0; nt < 4; nt++)
        bq20[nt] = *(const uint2*)(W2B + bOff[nt]);

    // Phase 3a: add staged (bias+phone+midi) from smem, per-row partial sums.
    {
        #pragma unroll
        for (int mt = 0; mt < 4; mt++) {
            const int r0 = mt * 16 + gid;
            const int r1 = r0 + 8;
            float s0 = 0.f, ss0 = 0.f, s1 = 0.f, ss1 = 0.f;
            #pragma unroll
            for (int nt = 0; nt < 4; nt++) {
                const int col = n0w + nt * 8 + q * 2;
                const float2 a0 = __half22float2(*(const __half2*)&sAdd[r0 * SA2H + col]);
                const float2 a1 = __half22float2(*(const __half2*)&sAdd[r1 * SA2H + col]);
                float x0 = acc[mt][nt][0] + a0.x;
                float x1 = acc[mt][nt][1] + a0.y;
                float x2 = acc[mt][nt][2] + a1.x;
                float x3 = acc[mt][nt][3] + a1.y;
                acc[mt][nt][0] = x0; acc[mt][nt][1] = x1;
                acc[mt][nt][2] = x2; acc[mt][nt][3] = x3;
                s0 += x0 + x1; ss0 += x0 * x0 + x1 * x1;
                s1 += x2 + x3; ss1 += x2 * x2 + x3 * x3;
            }
            #pragma unroll
            for (int o = 1; o < 4; o <<= 1) {
                s0 += __shfl_xor_sync(0xffffffffu, s0, o);
                ss0 += __shfl_xor_sync(0xffffffffu, ss0, o);
                s1 += __shfl_xor_sync(0xffffffffu, s1, o);
                ss1 += __shfl_xor_sync(0xffffffffu, ss1, o);
            }
            if (q == 0) {
                sPS[r0 * PS_STRIDE + w] = make_float2(s0, ss0);
                sPS[r1 * PS_STRIDE + w] = make_float2(s1, ss1);
            }
        }
    }
    __syncthreads();   // (2) partials ready

    // Phase 3b: finalize mu/rs per row (threads 0..63)
    if (tid < 64) {
        float s = 0.f, ss = 0.f;
        #pragma unroll
        for (int j = 0; j < 8; j++) {
            const float2 ps = sPS[tid * PS_STRIDE + j];
            s += ps.x; ss += ps.y;
        }
        const float mu = s * (1.f / 256.f);
        float var = ss * (1.f / 256.f) - mu * mu;
        var = fmaxf(var, 0.f);
        sMV[tid] = make_float2(mu, rsqrtf(var + EPS));
    }
    __syncthreads();   // (3) mu/rs ready

    // Phase 3c: apply LN + ReLU in-register, write half A2 tile
    {
        #pragma unroll
        for (int mt = 0; mt < 4; mt++) {
            const int r0 = mt * 16 + gid;
            const int r1 = r0 + 8;
            const float2 mv0 = sMV[r0];
            const float2 mv1 = sMV[r1];
            #pragma unroll
            for (int nt = 0; nt < 4; nt++) {
                const int col = n0w + nt * 8 + q * 2;
                const float2 gg = *(const float2*)&sg[col];
                const float2 bb = *(const float2*)&sb[col];
                float x0 = fmaxf((acc[mt][nt][0] - mv0.x) * mv0.y * gg.x + bb.x, 0.f);
                float x1 = fmaxf((acc[mt][nt][1] - mv0.x) * mv0.y * gg.y + bb.y, 0.f);
                float x2 = fmaxf((acc[mt][nt][2] - mv1.x) * mv1.y * gg.x + bb.x, 0.f);
                float x3 = fmaxf((acc[mt][nt][3] - mv1.x) * mv1.y * gg.y + bb.y, 0.f);
                *(__half2*)&sA2[r0 * SA2H + col] = __floats2half2_rn(x0, x1);
                *(__half2*)&sA2[r1 * SA2H + col] = __floats2half2_rn(x2, x3);
            }
        }
    }
    __syncthreads();   // (4) A2 ready

    #pragma unroll
    for (int mt = 0; mt < 4; mt++)
        #pragma unroll
        for (int nt = 0; nt < 4; nt++)
            #pragma unroll
            for (int e = 0; e < 4; e++) acc[mt][nt][e] = 0.f;

    // Phase 4: GEMM2 (K=256 -> 16 fp16 k-tiles), FULL unroll, imm addressing
    {
        uint2 bq[2][4];
        #pragma unroll
        for (int nt = 0; nt < 4; nt++)
            bq[0][nt] = bq20[nt];
        #pragma unroll
        for (int kt = 0; kt < 16; kt++) {
            const int cur = kt & 1, nxt = cur ^ 1;
            if (kt < 15) {
                #pragma unroll
                for (int nt = 0; nt < 4; nt++)
                    bq[nxt][nt] = *(const uint2*)(W2B + bOff[nt] + (kt + 1) * 8192);
            }
            unsigned a[4][4];
            #pragma unroll
            for (int mt = 0; mt < 4; mt++)
                ldsm_x4(a[mt][0], a[mt][1], a[mt][2], a[mt][3],
                        aBase2[mt] + (unsigned)(kt * 32));
            #pragma unroll
            for (int mt = 0; mt < 4; mt++)
                #pragma unroll
                for (int nt = 0; nt < 4; nt++)
                    mma_f16(acc[mt][nt], a[mt], (const unsigned*)&bq[cur][nt]);
        }
    }

    // Phase 5: write output (+proj_b2)
    #pragma unroll
    for (int mt = 0; mt < 4; mt++) {
        const int row = mt * 16 + gid;
        #pragma unroll
        for (int nt = 0; nt < 4; nt++) {
            const int col = n0w + nt * 8 + q * 2;
            const float b2a = sb2[col];
            const float b2b = sb2[col + 1];
            if (base + row < npos)
                *(float2*)&out[(size_t)(base + row) * 256 + col] =
                    make_float2(acc[mt][nt][0] + b2a, acc[mt][nt][1] + b2b);
            if (base + row + 8 < npos)
                *(float2*)&out[(size_t)(base + row + 8) * 256 + col] =
                    make_float2(acc[mt][nt][2] + b2a, acc[mt][nt][3] + b2b);
        }
    }
}

extern "C" void kernel_launch(void* const* d_in, const int* in_sizes, int n_in,
                              void* d_out, int out_size) {
    const float* f0          = (const float*)d_in[0];
    const int*   phone       = (const int*)  d_in[1];
    const float* duration    = (const float*)d_in[2];
    const int*   midi        = (const int*)  d_in[3];
    const float* f0_w1       = (const float*)d_in[4];
    const float* f0_b1       = (const float*)d_in[5];
    const float* f0_w2       = (const float*)d_in[6];
    const float* f0_b2       = (const float*)d_in[7];
    const float* phone_table = (const float*)d_in[8];
    const float* midi_table  = (const float*)d_in[9];
    const float* dur_w1      = (const float*)d_in[10];
    const float* dur_b1      = (const float*)d_in[11];
    const float* dur_w2      = (const float*)d_in[12];
    const float* dur_b2      = (const float*)d_in[13];
    const float* proj_w1     = (const float*)d_in[14];
    const float* proj_b1     = (const float*)d_in[15];
    const float* ln_g        = (const float*)d_in[16];
    const float* ln_b        = (const float*)d_in[17];
    const float* proj_w2     = (const float*)d_in[18];
    const float* proj_b2     = (const float*)d_in[19];
    float* out = (float*)d_out;
    const int npos = in_sizes[0];

    precompute_kernel<<<549, 256>>>(f0_w2, f0_b2, phone_table, midi_table,
                                    dur_w2, dur_b2, proj_w1, proj_b1, proj_w2);

    const size_t smem_bytes =
        (size_t)(64 * SA1H + 64 * SA2H * 2) * sizeof(__half) +
        (size_t)(64 * PS_STRIDE + 64) * sizeof(float2) +
        (size_t)(3 * 256) * sizeof(float) + 64;
    cudaFuncSetAttribute(cond_enc_mma_kernel,
                         cudaFuncAttributeMaxDynamicSharedMemorySize,
                         (int)smem_bytes);
    const int grid = (npos + TM - 1) / TM;
    cond_enc_mma_kernel<<<grid, 256, smem_bytes>>>(
        f0, phone, duration, midi, f0_w1, f0_b1, dur_w1, dur_b1,
        ln_g, ln_b, proj_b2, out, npos);
}

// round 14
// speedup vs baseline: 1.1615x; 1.0202x over previous
#include <cuda_runtime.h>
#include <cuda_fp16.h>

#define TM 64
#define EPS 1e-5f

#define SA2H 264   // [64][264] halves: row step 528B == 16B mod 128B
#define PS_STRIDE 9

// ---------------- device scratch ----------------
__device__ __align__(16) __half g_phonePh[100 * 256];   // fp16 folded phone table
__device__ __align__(16) __half g_midiPh[128 * 256];    // fp16 folded midi table
__device__ __align__(16) float g_bias[256];
// Pair-packed fp16 B fragments: halves index
//   (kt*16 + w*2 + pair)*256 + (gid*4 + qq)*8 + hs*4 + rr
// so lane (gid,q) of warp w reads ONE uint4 per (kt, pair) containing the
// fragments for nt=2*pair (low 8B) and nt=2*pair+1 (high 8B).
__device__ __align__(16) __half g_W1H[4 * 256 * 16];    // K=64  -> 4 k-tiles
__device__ __align__(16) __half g_W2H[16 * 256 * 16];   // K=256 -> 16 k-tiles

__host__ __device__ __forceinline__ int slot16(int kk) {
    return ((kk & 7) >> 1) * 4 + ((kk >> 3) & 1) * 2 + (kk & 1);
}

// pair-packed half index for (kt, k-within-16, out-col n)
__host__ __device__ __forceinline__ int packB(int kt, int kk, int n) {
    const int slot = slot16(kk);
    const int w = n >> 5, gid = n & 7, nt = (n >> 3) & 3;
    return (kt * 16 + w * 2 + (nt >> 1)) * 256 + (gid * 4 + (slot >> 2)) * 8 +
           (nt & 1) * 4 + (slot & 3);
}

__device__ __forceinline__ unsigned smem_u32(const void* p) {
    unsigned a;
    asm("{ .reg .u64 t; cvta.to.shared.u64 t, %1; cvt.u32.u64 %0, t; }"
        : "=r"(a) : "l"(p));
    return a;
}

__device__ __forceinline__ void ldsm_x4(unsigned& r0, unsigned& r1,
                                        unsigned& r2, unsigned& r3,
                                        unsigned addr) {
    asm volatile("ldmatrix.sync.aligned.m8n8.x4.shared.b16 {%0,%1,%2,%3}, [%4];"
                 : "=r"(r0), "=r"(r1), "=r"(r2), "=r"(r3) : "r"(addr));
}

__device__ __forceinline__ void mma_f16(float* c, const unsigned* a,
                                        unsigned b0, unsigned b1) {
    asm volatile(
        "mma.sync.aligned.m16n8k16.row.col.f32.f16.f16.f32 "
        "{%0,%1,%2,%3}, {%4,%5,%6,%7}, {%8,%9}, {%0,%1,%2,%3};"
        : "+f"(c[0]), "+f"(c[1]), "+f"(c[2]), "+f"(c[3])
        : "r"(a[0]), "r"(a[1]), "r"(a[2]), "r"(a[3]), "r"(b0), "r"(b1));
}

__device__ __forceinline__ unsigned h2u(float x, float y) {
    __half2 h = __floats2half2_rn(x, y);
    return *reinterpret_cast<unsigned*>(&h);
}

// ---------------- precompute ----------------
__global__ void precompute_kernel(
    const float* __restrict__ f0_w2, const float* __restrict__ f0_b2,
    const float* __restrict__ phone_table, const float* __restrict__ midi_table,
    const float* __restrict__ dur_w2, const float* __restrict__ dur_b2,
    const float* __restrict__ proj_w1, const float* __restrict__ proj_b1,
    const float* __restrict__ proj_w2) {
    const int r = blockIdx.x;
    const int c = threadIdx.x;
    if (r < 100) {
        float s0 = 0.f, s1 = 0.f, s2 = 0.f, s3 = 0.f;
        #pragma unroll 8
        for (int k = 0; k < 128; k += 4) {
            s0 += phone_table[r * 128 + k + 0] * proj_w1[(64 + k + 0) * 256 + c];
            s1 += phone_table[r * 128 + k + 1] * proj_w1[(64 + k + 1) * 256 + c];
            s2 += phone_table[r * 128 + k + 2] * proj_w1[(64 + k + 2) * 256 + c];
            s3 += phone_table[r * 128 + k + 3] * proj_w1[(64 + k + 3) * 256 + c];
        }
        g_phonePh[r * 256 + c] = __float2half_rn((s0 + s1) + (s2 + s3));
    } else if (r < 228) {
        const int m = r - 100;
        float s0 = 0.f, s1 = 0.f, s2 = 0.f, s3 = 0.f;
        #pragma unroll 4
        for (int k = 0; k < 64; k += 4) {
            s0 += midi_table[m * 64 + k + 0] * proj_w1[(192 + k + 0) * 256 + c];
            s1 += midi_table[m * 64 + k + 1] * proj_w1[(192 + k + 1) * 256 + c];
            s2 += midi_table[m * 64 + k + 2] * proj_w1[(192 + k + 2) * 256 + c];
            s3 += midi_table[m * 64 + k + 3] * proj_w1[(192 + k + 3) * 256 + c];
        }
        g_midiPh[m * 256 + c] = __float2half_rn((s0 + s1) + (s2 + s3));
    } else if (r < 260) {
        const int kd = r - 228;          // derived-K 0..31 (f0 part)
        float s0 = 0.f, s1 = 0.f, s2 = 0.f, s3 = 0.f;
        #pragma unroll 4
        for (int k = 0; k < 64; k += 4) {
            s0 += f0_w2[kd * 64 + k + 0] * proj_w1[(k + 0) * 256 + c];
            s1 += f0_w2[kd * 64 + k + 1] * proj_w1[(k + 1) * 256 + c];
            s2 += f0_w2[kd * 64 + k + 2] * proj_w1[(k + 2) * 256 + c];
            s3 += f0_w2[kd * 64 + k + 3] * proj_w1[(k + 3) * 256 + c];
        }
        g_W1H[packB(kd >> 4, kd & 15, c)] = __float2half_rn((s0 + s1) + (s2 + s3));
    } else if (r < 292) {
        const int j = r - 260;           // dur part -> derived-K 32..63
        const int kd = 32 + j;
        float s0 = 0.f, s1 = 0.f, s2 = 0.f, s3 = 0.f;
        #pragma unroll 4
        for (int k = 0; k < 64; k += 4) {
            s0 += dur_w2[j * 64 + k + 0] * proj_w1[(256 + k + 0) * 256 + c];
            s1 += dur_w2[j * 64 + k + 1] * proj_w1[(256 + k + 1) * 256 + c];
            s2 += dur_w2[j * 64 + k + 2] * proj_w1[(256 + k + 2) * 256 + c];
            s3 += dur_w2[j * 64 + k + 3] * proj_w1[(256 + k + 3) * 256 + c];
        }
        g_W1H[packB(kd >> 4, kd & 15, c)] = __float2half_rn((s0 + s1) + (s2 + s3));
    } else if (r < 293) {
        float s = proj_b1[c];
        #pragma unroll 4
        for (int k = 0; k < 64; k++) {
            s += f0_b2[k] * proj_w1[k * 256 + c];
            s += dur_b2[k] * proj_w1[(256 + k) * 256 + c];
        }
        g_bias[c] = s;
    } else {
        const int k = r - 293;           // 0..255: proj_w2 input-row k, col c
        g_W2H[packB(k >> 4, k & 15, c)] = __float2half_rn(proj_w2[k * 256 + c]);
    }
}

// ---------------- main fused fp16-mma kernel (2 CTAs/SM, TM=64) ----------------
__global__ __launch_bounds__(256, 2)
void cond_enc_mma_kernel(
    const float* __restrict__ f0, const int* __restrict__ phone,
    const float* __restrict__ duration, const int* __restrict__ midi,
    const float* __restrict__ f0_w1, const float* __restrict__ f0_b1,
    const float* __restrict__ dur_w1, const float* __restrict__ dur_b1,
    const float* __restrict__ ln_g, const float* __restrict__ ln_b,
    const float* __restrict__ proj_b2,
    float* __restrict__ out, int npos) {
    extern __shared__ __align__(16) char smraw[];
    __half* sA2 = (__half*)smraw;                       // [64][264]
    __half* sAdd = sA2 + 64 * SA2H;                     // [64][264] bias+phone+midi
    float2* sPS = (float2*)(sAdd + 64 * SA2H);          // [64][9] partials
    float2* sMV = sPS + 64 * PS_STRIDE;                 // [64] (mu, rs)
    float* sg = (float*)(sMV + 64);                     // [256]
    float* sb = sg + 256;
    float* sb2 = sb + 256;

    const int tid = threadIdx.x;
    const int lane = tid & 31;
    const int w = tid >> 5;          // warp w owns cols [w*32, w*32+32), all 64 rows
    const int n0w = w * 32;
    const int gid = lane >> 2;
    const int q = lane & 3;
    const int base = blockIdx.x * TM;

    // ldmatrix per-lane A offsets (b16, 16-k tiles) for GEMM2 only
    const int tA = lane >> 3;
    const int aRow = (lane & 7) + (tA & 1) * 8;
    const int aKof = (tA >> 1) * 8;       // halves

    const unsigned u_sA2 = smem_u32(sA2);

    // Pair-packed B byte offsets: frag pair p at  base + pOff[p] + kt*8192
    unsigned pOff[2];
    #pragma unroll
    for (int p = 0; p < 2; p++)
        pOff[p] = (unsigned)((w * 2 + p) * 512 + (gid * 4 + q) * 16);
    const char* __restrict__ W1B = (const char*)g_W1H;
    const char* __restrict__ W2B = (const char*)g_W2H;

    unsigned aBase2[4];
    #pragma unroll
    for (int mt = 0; mt < 4; mt++)
        aBase2[mt] = u_sA2 + (unsigned)(((mt * 16 + aRow) * SA2H + aKof) * 2);

    // Preload GEMM1 B kt=0 immediately (hidden behind phase 1a).
    uint4 bq4[2][2];
    #pragma unroll
    for (int p = 0; p < 2; p++)
        bq4[0][p] = *(const uint4*)(W1B + pOff[p]);

    sg[tid] = ln_g[tid];
    sb[tid] = ln_b[tid];
    sb2[tid] = proj_b2[tid];

    // Phase 1a: coalesced table staging. Warp w handles rows w*8..w*8+7:
    // sAdd[r][c] = fp16( g_bias[c] + phoneP[p][c] + midiP[m][c] ), 128B accesses.
    #pragma unroll 2
    for (int rr = 0; rr < 8; rr++) {
        const int r = w * 8 + rr;
        int grow = base + r; if (grow >= npos) grow = npos - 1;
        const __half2* __restrict__ pp = (const __half2*)&g_phonePh[phone[grow] * 256];
        const __half2* __restrict__ mp = (const __half2*)&g_midiPh[midi[grow] * 256];
        const float2* __restrict__ bb = (const float2*)g_bias;
        #pragma unroll
        for (int h = 0; h < 4; h++) {
            const int c2 = lane + 32 * h;        // half2 index 0..127
            const float2 a = __half22float2(pp[c2]);
            const float2 b = __half22float2(mp[c2]);
            const float2 d = bb[c2];
            *(__half2*)&sAdd[r * SA2H + c2 * 2] =
                __floats2half2_rn(d.x + a.x + b.x, d.y + a.y + b.y);
        }
    }

    float acc[4][4][4];
    #pragma unroll
    for (int mt = 0; mt < 4; mt++)
        #pragma unroll
        for (int nt = 0; nt < 4; nt++)
            #pragma unroll
            for (int e = 0; e < 4; e++) acc[mt][nt][e] = 0.f;

    // Phase 2: GEMM1 with DIRECT A-fragment compute (no smem A, no LDSM).
    // kt 0,1 use f0; kt 2,3 use duration.  A frag: rows {mt*16+gid, +8},
    // k = kt*16 + {2q,2q+1} (a0/a1) and {2q+8,2q+9} (a2/a3).
    {
        float xs[8];
        #pragma unroll
        for (int ktp = 0; ktp < 2; ktp++) {
            const float* __restrict__ src = ktp ? duration : f0;
            const float* __restrict__ w1v = ktp ? dur_w1 : f0_w1;
            const float* __restrict__ b1v = ktp ? dur_b1 : f0_b1;
            #pragma unroll
            for (int mt = 0; mt < 4; mt++) {
                int r0 = base + mt * 16 + gid;     if (r0 >= npos) r0 = npos - 1;
                int r1 = base + mt * 16 + gid + 8; if (r1 >= npos) r1 = npos - 1;
                xs[2 * mt] = src[r0];
                xs[2 * mt + 1] = src[r1];
            }
            #pragma unroll
            for (int kth = 0; kth < 2; kth++) {
                const int kt = ktp * 2 + kth;
                const int cur = kt & 1, nxt = cur ^ 1;
                if (kt < 3) {
                    #pragma unroll
                    for (int p = 0; p < 2; p++)
                        bq4[nxt][p] = *(const uint4*)(W1B + pOff[p] + (kt + 1) * 8192);
                }
                const int u0 = kth * 16 + 2 * q;
                const float2 wA = *(const float2*)&w1v[u0];
                const float2 bA = *(const float2*)&b1v[u0];
                const float2 wB = *(const float2*)&w1v[u0 + 8];
                const float2 bB = *(const float2*)&b1v[u0 + 8];
                unsigned a[4][4];
                #pragma unroll
                for (int mt = 0; mt < 4; mt++) {
                    const float x0 = xs[2 * mt], x1 = xs[2 * mt + 1];
                    a[mt][0] = h2u(fmaxf(x0 * wA.x + bA.x, 0.f),
                                   fmaxf(x0 * wA.y + bA.y, 0.f));
                    a[mt][1] = h2u(fmaxf(x1 * wA.x + bA.x, 0.f),
                                   fmaxf(x1 * wA.y + bA.y, 0.f));
                    a[mt][2] = h2u(fmaxf(x0 * wB.x + bB.x, 0.f),
                                   fmaxf(x0 * wB.y + bB.y, 0.f));
                    a[mt][3] = h2u(fmaxf(x1 * wB.x + bB.x, 0.f),
                                   fmaxf(x1 * wB.y + bB.y, 0.f));
                }
                #pragma unroll
                for (int mt = 0; mt < 4; mt++) {
                    mma_f16(acc[mt][0], a[mt], bq4[cur][0].x, bq4[cur][0].y);
                    mma_f16(acc[mt][1], a[mt], bq4[cur][0].z, bq4[cur][0].w);
                    mma_f16(acc[mt][2], a[mt], bq4[cur][1].x, bq4[cur][1].y);
                    mma_f16(acc[mt][3], a[mt], bq4[cur][1].z, bq4[cur][1].w);
                }
            }
        }
    }

    // Early prefetch of GEMM2's first B k-tile — hidden behind the LN phase.
    uint4 bq20[2];
    #pragma unroll
    for (int p = 0; p < 2; p++)
        bq20[p] = *(const uint4*)(W2B + pOff[p]);

    __syncthreads();   // (1) sAdd ready (also orders nothing else now)

    // Phase 3a: add staged (bias+phone+midi) from smem, per-row partial sums.
    {
        #pragma unroll
        for (int mt = 0; mt < 4; mt++) {
            const int r0 = mt * 16 + gid;
            const int r1 = r0 + 8;
            float s0 = 0.f, ss0 = 0.f, s1 = 0.f, ss1 = 0.f;
            #pragma unroll
            for (int nt = 0; nt < 4; nt++) {
                const int col = n0w + nt * 8 + q * 2;
                const float2 a0 = __half22float2(*(const __half2*)&sAdd[r0 * SA2H + col]);
                const float2 a1 = __half22float2(*(const __half2*)&sAdd[r1 * SA2H + col]);
                float x0 = acc[mt][nt][0] + a0.x;
                float x1 = acc[mt][nt][1] + a0.y;
                float x2 = acc[mt][nt][2] + a1.x;
                float x3 = acc[mt][nt][3] + a1.y;
                acc[mt][nt][0] = x0; acc[mt][nt][1] = x1;
                acc[mt][nt][2] = x2; acc[mt][nt][3] = x3;
                s0 += x0 + x1; ss0 += x0 * x0 + x1 * x1;
                s1 += x2 + x3; ss1 += x2 * x2 + x3 * x3;
            }
            #pragma unroll
            for (int o = 1; o < 4; o <<= 1) {
                s0 += __shfl_xor_sync(0xffffffffu, s0, o);
                ss0 += __shfl_xor_sync(0xffffffffu, ss0, o);
                s1 += __shfl_xor_sync(0xffffffffu, s1, o);
                ss1 += __shfl_xor_sync(0xffffffffu, ss1, o);
            }
            if (q == 0) {
                sPS[r0 * PS_STRIDE + w] = make_float2(s0, ss0);
                sPS[r1 * PS_STRIDE + w] = make_float2(s1, ss1);
            }
        }
    }
    __syncthreads();   // (2) partials ready

    // Phase 3b: finalize mu/rs per row (threads 0..63)
    if (tid < 64) {
        float s = 0.f, ss = 0.f;
        #pragma unroll
        for (int j = 0; j < 8; j++) {
            const float2 ps = sPS[tid * PS_STRIDE + j];
            s += ps.x; ss += ps.y;
        }
        const float mu = s * (1.f / 256.f);
        float var = ss * (1.f / 256.f) - mu * mu;
        var = fmaxf(var, 0.f);
        sMV[tid] = make_float2(mu, rsqrtf(var + EPS));
    }
    __syncthreads();   // (3) mu/rs ready

    // Phase 3c: apply LN + ReLU in-register, write half A2 tile
    {
        #pragma unroll
        for (int mt = 0; mt < 4; mt++) {
            const int r0 = mt * 16 + gid;
            const int r1 = r0 + 8;
            const float2 mv0 = sMV[r0];
            const float2 mv1 = sMV[r1];
            #pragma unroll
            for (int nt = 0; nt < 4; nt++) {
                const int col = n0w + nt * 8 + q * 2;
                const float2 gg = *(const float2*)&sg[col];
                const float2 bb = *(const float2*)&sb[col];
                float x0 = fmaxf((acc[mt][nt][0] - mv0.x) * mv0.y * gg.x + bb.x, 0.f);
                float x1 = fmaxf((acc[mt][nt][1] - mv0.x) * mv0.y * gg.y + bb.y, 0.f);
                float x2 = fmaxf((acc[mt][nt][2] - mv1.x) * mv1.y * gg.x + bb.x, 0.f);
                float x3 = fmaxf((acc[mt][nt][3] - mv1.x) * mv1.y * gg.y + bb.y, 0.f);
                *(__half2*)&sA2[r0 * SA2H + col] = __floats2half2_rn(x0, x1);
                *(__half2*)&sA2[r1 * SA2H + col] = __floats2half2_rn(x2, x3);
            }
        }
    }
    __syncthreads();   // (4) A2 ready

    #pragma unroll
    for (int mt = 0; mt < 4; mt++)
        #pragma unroll
        for (int nt = 0; nt < 4; nt++)
            #pragma unroll
            for (int e = 0; e < 4; e++) acc[mt][nt][e] = 0.f;

    // Phase 4: GEMM2 (K=256 -> 16 fp16 k-tiles), FULL unroll, paired LDG.128 B
    {
        bq4[0][0] = bq20[0];
        bq4[0][1] = bq20[1];
        #pragma unroll
        for (int kt = 0; kt < 16; kt++) {
            const int cur = kt & 1, nxt = cur ^ 1;
            if (kt < 15) {
                #pragma unroll
                for (int p = 0; p < 2; p++)
                    bq4[nxt][p] = *(const uint4*)(W2B + pOff[p] + (kt + 1) * 8192);
            }
            unsigned a[4][4];
            #pragma unroll
            for (int mt = 0; mt < 4; mt++)
                ldsm_x4(a[mt][0], a[mt][1], a[mt][2], a[mt][3],
                        aBase2[mt] + (unsigned)(kt * 32));
            #pragma unroll
            for (int mt = 0; mt < 4; mt++) {
                mma_f16(acc[mt][0], a[mt], bq4[cur][0].x, bq4[cur][0].y);
                mma_f16(acc[mt][1], a[mt], bq4[cur][0].z, bq4[cur][0].w);
                mma_f16(acc[mt][2], a[mt], bq4[cur][1].x, bq4[cur][1].y);
                mma_f16(acc[mt][3], a[mt], bq4[cur][1].z, bq4[cur][1].w);
            }
        }
    }

    // Phase 5: write output (+proj_b2)
    #pragma unroll
    for (int mt = 0; mt < 4; mt++) {
        const int row = mt * 16 + gid;
        #pragma unroll
        for (int nt = 0; nt < 4; nt++) {
            const int col = n0w + nt * 8 + q * 2;
            const float b2a = sb2[col];
            const float b2b = sb2[col + 1];
            if (base + row < npos)
                *(float2*)&out[(size_t)(base + row) * 256 + col] =
                    make_float2(acc[mt][nt][0] + b2a, acc[mt][nt][1] + b2b);
            if (base + row + 8 < npos)
                *(float2*)&out[(size_t)(base + row + 8) * 256 + col] =
                    make_float2(acc[mt][nt][2] + b2a, acc[mt][nt][3] + b2b);
        }
    }
}

extern "C" void kernel_launch(void* const* d_in, const int* in_sizes, int n_in,
                              void* d_out, int out_size) {
    const float* f0          = (const float*)d_in[0];
    const int*   phone       = (const int*)  d_in[1];
    const float* duration    = (const float*)d_in[2];
    const int*   midi        = (const int*)  d_in[3];
    const float* f0_w1       = (const float*)d_in[4];
    const float* f0_b1       = (const float*)d_in[5];
    const float* f0_w2       = (const float*)d_in[6];
    const float* f0_b2       = (const float*)d_in[7];
    const float* phone_table = (const float*)d_in[8];
    const float* midi_table  = (const float*)d_in[9];
    const float* dur_w1      = (const float*)d_in[10];
    const float* dur_b1      = (const float*)d_in[11];
    const float* dur_w2      = (const float*)d_in[12];
    const float* dur_b2      = (const float*)d_in[13];
    const float* proj_w1     = (const float*)d_in[14];
    const float* proj_b1     = (const float*)d_in[15];
    const float* ln_g        = (const float*)d_in[16];
    const float* ln_b        = (const float*)d_in[17];
    const float* proj_w2     = (const float*)d_in[18];
    const float* proj_b2     = (const float*)d_in[19];
    float* out = (float*)d_out;
    const int npos = in_sizes[0];

    precompute_kernel<<<549, 256>>>(f0_w2, f0_b2, phone_table, midi_table,
                                    dur_w2, dur_b2, proj_w1, proj_b1, proj_w2);

    const size_t smem_bytes =
        (size_t)(64 * SA2H * 2) * sizeof(__half) +
        (size_t)(64 * PS_STRIDE + 64) * sizeof(float2) +
        (size_t)(3 * 256) * sizeof(float) + 64;
    cudaFuncSetAttribute(cond_enc_mma_kernel,
                         cudaFuncAttributeMaxDynamicSharedMemorySize,
                         (int)smem_bytes);
    const int grid = (npos + TM - 1) / TM;
    cond_enc_mma_kernel<<<grid, 256, smem_bytes>>>(
        f0, phone, duration, midi, f0_w1, f0_b1, dur_w1, dur_b1,
        ln_g, ln_b, proj_b2, out, npos);
}

// round 15
// speedup vs baseline: 1.1746x; 1.0113x over previous
#include <cuda_runtime.h>
#include <cuda_fp16.h>

#define TM 64
#define EPS 1e-5f

#define SA2H 264   // [64][264] halves: row step 528B == 16B mod 128B
#define PS_STRIDE 9

// ---------------- device scratch ----------------
__device__ __align__(16) __half g_phonePh[100 * 256];   // fp16 folded phone table
__device__ __align__(16) __half g_midiPh[128 * 256];    // fp16 folded midi table
__device__ __align__(16) float g_bias[256];
// Pair-packed fp16 B fragments: halves index
//   (kt*16 + w*2 + pair)*256 + (gid*4 + qq)*8 + hs*4 + rr
// Lane (gid,q) of warp w reads ONE uint4 per (kt, pair); warp w's whole k-tile
// is the contiguous 1024B block at  base + kt*8192 + w*1024.
__device__ __align__(16) __half g_W1H[4 * 256 * 16];    // K=64  -> 4 k-tiles
__device__ __align__(16) __half g_W2H[16 * 256 * 16];   // K=256 -> 16 k-tiles

__host__ __device__ __forceinline__ int slot16(int kk) {
    return ((kk & 7) >> 1) * 4 + ((kk >> 3) & 1) * 2 + (kk & 1);
}

// pair-packed half index for (kt, k-within-16, out-col n)
__host__ __device__ __forceinline__ int packB(int kt, int kk, int n) {
    const int slot = slot16(kk);
    const int w = n >> 5, gid = n & 7, nt = (n >> 3) & 3;
    return (kt * 16 + w * 2 + (nt >> 1)) * 256 + (gid * 4 + (slot >> 2)) * 8 +
           (nt & 1) * 4 + (slot & 3);
}

__device__ __forceinline__ unsigned smem_u32(const void* p) {
    unsigned a;
    asm("{ .reg .u64 t; cvta.to.shared.u64 t, %1; cvt.u32.u64 %0, t; }"
        : "=r"(a) : "l"(p));
    return a;
}

__device__ __forceinline__ void ldsm_x4(unsigned& r0, unsigned& r1,
                                        unsigned& r2, unsigned& r3,
                                        unsigned addr) {
    asm volatile("ldmatrix.sync.aligned.m8n8.x4.shared.b16 {%0,%1,%2,%3}, [%4];"
                 : "=r"(r0), "=r"(r1), "=r"(r2), "=r"(r3) : "r"(addr));
}

__device__ __forceinline__ void mma_f16(float* c, const unsigned* a,
                                        unsigned b0, unsigned b1) {
    asm volatile(
        "mma.sync.aligned.m16n8k16.row.col.f32.f16.f16.f32 "
        "{%0,%1,%2,%3}, {%4,%5,%6,%7}, {%8,%9}, {%0,%1,%2,%3};"
        : "+f"(c[0]), "+f"(c[1]), "+f"(c[2]), "+f"(c[3])
        : "r"(a[0]), "r"(a[1]), "r"(a[2]), "r"(a[3]), "r"(b0), "r"(b1));
}

__device__ __forceinline__ unsigned h2u(float x, float y) {
    __half2 h = __floats2half2_rn(x, y);
    return *reinterpret_cast<unsigned*>(&h);
}

__device__ __forceinline__ void cp16(unsigned saddr, const void* g) {
    asm volatile("cp.async.cg.shared.global [%0], [%1], 16;" :: "r"(saddr), "l"(g));
}
__device__ __forceinline__ void cp_commit() {
    asm volatile("cp.async.commit_group;" ::: "memory");
}
__device__ __forceinline__ void cp_wait3() {
    asm volatile("cp.async.wait_group 3;" ::: "memory");
}

__device__ __forceinline__ uint4 lds128(unsigned addr) {
    uint4 v;
    asm volatile("ld.shared.v4.u32 {%0,%1,%2,%3}, [%4];"
                 : "=r"(v.x), "=r"(v.y), "=r"(v.z), "=r"(v.w) : "r"(addr));
    return v;
}

// ---------------- precompute ----------------
__global__ void precompute_kernel(
    const float* __restrict__ f0_w2, const float* __restrict__ f0_b2,
    const float* __restrict__ phone_table, const float* __restrict__ midi_table,
    const float* __restrict__ dur_w2, const float* __restrict__ dur_b2,
    const float* __restrict__ proj_w1, const float* __restrict__ proj_b1,
    const float* __restrict__ proj_w2) {
    const int r = blockIdx.x;
    const int c = threadIdx.x;
    if (r < 100) {
        float s0 = 0.f, s1 = 0.f, s2 = 0.f, s3 = 0.f;
        #pragma unroll 8
        for (int k = 0; k < 128; k += 4) {
            s0 += phone_table[r * 128 + k + 0] * proj_w1[(64 + k + 0) * 256 + c];
            s1 += phone_table[r * 128 + k + 1] * proj_w1[(64 + k + 1) * 256 + c];
            s2 += phone_table[r * 128 + k + 2] * proj_w1[(64 + k + 2) * 256 + c];
            s3 += phone_table[r * 128 + k + 3] * proj_w1[(64 + k + 3) * 256 + c];
        }
        g_phonePh[r * 256 + c] = __float2half_rn((s0 + s1) + (s2 + s3));
    } else if (r < 228) {
        const int m = r - 100;
        float s0 = 0.f, s1 = 0.f, s2 = 0.f, s3 = 0.f;
        #pragma unroll 4
        for (int k = 0; k < 64; k += 4) {
            s0 += midi_table[m * 64 + k + 0] * proj_w1[(192 + k + 0) * 256 + c];
            s1 += midi_table[m * 64 + k + 1] * proj_w1[(192 + k + 1) * 256 + c];
            s2 += midi_table[m * 64 + k + 2] * proj_w1[(192 + k + 2) * 256 + c];
            s3 += midi_table[m * 64 + k + 3] * proj_w1[(192 + k + 3) * 256 + c];
        }
        g_midiPh[m * 256 + c] = __float2half_rn((s0 + s1) + (s2 + s3));
    } else if (r < 260) {
        const int kd = r - 228;          // derived-K 0..31 (f0 part)
        float s0 = 0.f, s1 = 0.f, s2 = 0.f, s3 = 0.f;
        #pragma unroll 4
        for (int k = 0; k < 64; k += 4) {
            s0 += f0_w2[kd * 64 + k + 0] * proj_w1[(k + 0) * 256 + c];
            s1 += f0_w2[kd * 64 + k + 1] * proj_w1[(k + 1) * 256 + c];
            s2 += f0_w2[kd * 64 + k + 2] * proj_w1[(k + 2) * 256 + c];
            s3 += f0_w2[kd * 64 + k + 3] * proj_w1[(k + 3) * 256 + c];
        }
        g_W1H[packB(kd >> 4, kd & 15, c)] = __float2half_rn((s0 + s1) + (s2 + s3));
    } else if (r < 292) {
        const int j = r - 260;           // dur part -> derived-K 32..63
        const int kd = 32 + j;
        float s0 = 0.f, s1 = 0.f, s2 = 0.f, s3 = 0.f;
        #pragma unroll 4
        for (int k = 0; k < 64; k += 4) {
            s0 += dur_w2[j * 64 + k + 0] * proj_w1[(256 + k + 0) * 256 + c];
            s1 += dur_w2[j * 64 + k + 1] * proj_w1[(256 + k + 1) * 256 + c];
            s2 += dur_w2[j * 64 + k + 2] * proj_w1[(256 + k + 2) * 256 + c];
            s3 += dur_w2[j * 64 + k + 3] * proj_w1[(256 + k + 3) * 256 + c];
        }
        g_W1H[packB(kd >> 4, kd & 15, c)] = __float2half_rn((s0 + s1) + (s2 + s3));
    } else if (r < 293) {
        float s = proj_b1[c];
        #pragma unroll 4
        for (int k = 0; k < 64; k++) {
            s += f0_b2[k] * proj_w1[k * 256 + c];
            s += dur_b2[k] * proj_w1[(256 + k) * 256 + c];
        }
        g_bias[c] = s;
    } else {
        const int k = r - 293;           // 0..255: proj_w2 input-row k, col c
        g_W2H[packB(k >> 4, k & 15, c)] = __float2half_rn(proj_w2[k * 256 + c]);
    }
}

// ---------------- main fused fp16-mma kernel (2 CTAs/SM, TM=64) ----------------
__global__ __launch_bounds__(256, 2)
void cond_enc_mma_kernel(
    const float* __restrict__ f0, const int* __restrict__ phone,
    const float* __restrict__ duration, const int* __restrict__ midi,
    const float* __restrict__ f0_w1, const float* __restrict__ f0_b1,
    const float* __restrict__ dur_w1, const float* __restrict__ dur_b1,
    const float* __restrict__ ln_g, const float* __restrict__ ln_b,
    const float* __restrict__ proj_b2,
    float* __restrict__ out, int npos) {
    extern __shared__ __align__(16) char smraw[];
    // sA2 and sAdd SHARE one buffer: all sAdd reads precede barrier (2);
    // all sA2 writes follow barrier (3). Disjoint lifetimes.
    __half* sA2 = (__half*)smraw;                       // [64][264]
    __half* sAdd = sA2;                                 // alias (see above)
    char* sRing = (char*)(sA2 + 64 * SA2H);             // 8 warps x 4 slots x 1024B
    float2* sPS = (float2*)(sRing + 8 * 4096);          // [64][9] partials
    float2* sMV = sPS + 64 * PS_STRIDE;                 // [64] (mu, rs)
    float* sg = (float*)(sMV + 64);                     // [256]
    float* sb = sg + 256;
    float* sb2 = sb + 256;

    const int tid = threadIdx.x;
    const int lane = tid & 31;
    const int w = tid >> 5;          // warp w owns cols [w*32, w*32+32), all 64 rows
    const int n0w = w * 32;
    const int gid = lane >> 2;
    const int q = lane & 3;
    const int base = blockIdx.x * TM;

    // ldmatrix per-lane A offsets (b16, 16-k tiles) for GEMM2 only
    const int tA = lane >> 3;
    const int aRow = (lane & 7) + (tA & 1) * 8;
    const int aKof = (tA >> 1) * 8;       // halves

    const unsigned u_sA2 = smem_u32(sA2);
    const unsigned u_ring = smem_u32(sRing);

    // Pair-packed B byte offsets (register path, GEMM1 only):
    unsigned pOff[2];
    #pragma unroll
    for (int p = 0; p < 2; p++)
        pOff[p] = (unsigned)((w * 2 + p) * 512 + (gid * 4 + q) * 16);
    const char* __restrict__ W1B = (const char*)g_W1H;
    const char* __restrict__ W2B = (const char*)g_W2H;

    unsigned aBase2[4];
    #pragma unroll
    for (int mt = 0; mt < 4; mt++)
        aBase2[mt] = u_sA2 + (unsigned)(((mt * 16 + aRow) * SA2H + aKof) * 2);

    // Preload GEMM1 B kt=0 immediately (hidden behind phase 1a).
    uint4 bq4[2][2];
    #pragma unroll
    for (int p = 0; p < 2; p++)
        bq4[0][p] = *(const uint4*)(W1B + pOff[p]);

    sg[tid] = ln_g[tid];
    sb[tid] = ln_b[tid];
    sb2[tid] = proj_b2[tid];

    // Phase 1a: coalesced table staging. Warp w handles rows w*8..w*8+7:
    // sAdd[r][c] = fp16( g_bias[c] + phoneP[p][c] + midiP[m][c] ), 128B accesses.
    #pragma unroll 2
    for (int rr = 0; rr < 8; rr++) {
        const int r = w * 8 + rr;
        int grow = base + r; if (grow >= npos) grow = npos - 1;
        const __half2* __restrict__ pp = (const __half2*)&g_phonePh[phone[grow] * 256];
        const __half2* __restrict__ mp = (const __half2*)&g_midiPh[midi[grow] * 256];
        const float2* __restrict__ bb = (const float2*)g_bias;
        #pragma unroll
        for (int h = 0; h < 4; h++) {
            const int c2 = lane + 32 * h;        // half2 index 0..127
            const float2 a = __half22float2(pp[c2]);
            const float2 b = __half22float2(mp[c2]);
            const float2 d = bb[c2];
            *(__half2*)&sAdd[r * SA2H + c2 * 2] =
                __floats2half2_rn(d.x + a.x + b.x, d.y + a.y + b.y);
        }
    }

    float acc[4][4][4];
    #pragma unroll
    for (int mt = 0; mt < 4; mt++)
        #pragma unroll
        for (int nt = 0; nt < 4; nt++)
            #pragma unroll
            for (int e = 0; e < 4; e++) acc[mt][nt][e] = 0.f;

    // Phase 2: GEMM1 with DIRECT A-fragment compute (no smem A, no LDSM).
    {
        float xs[8];
        #pragma unroll
        for (int ktp = 0; ktp < 2; ktp++) {
            const float* __restrict__ src = ktp ? duration : f0;
            const float* __restrict__ w1v = ktp ? dur_w1 : f0_w1;
            const float* __restrict__ b1v = ktp ? dur_b1 : f0_b1;
            #pragma unroll
            for (int mt = 0; mt < 4; mt++) {
                int r0 = base + mt * 16 + gid;     if (r0 >= npos) r0 = npos - 1;
                int r1 = base + mt * 16 + gid + 8; if (r1 >= npos) r1 = npos - 1;
                xs[2 * mt] = src[r0];
                xs[2 * mt + 1] = src[r1];
            }
            #pragma unroll
            for (int kth = 0; kth < 2; kth++) {
                const int kt = ktp * 2 + kth;
                const int cur = kt & 1, nxt = cur ^ 1;
                if (kt < 3) {
                    #pragma unroll
                    for (int p = 0; p < 2; p++)
                        bq4[nxt][p] = *(const uint4*)(W1B + pOff[p] + (kt + 1) * 8192);
                }
                const int u0 = kth * 16 + 2 * q;
                const float2 wA = *(const float2*)&w1v[u0];
                const float2 bA = *(const float2*)&b1v[u0];
                const float2 wB = *(const float2*)&w1v[u0 + 8];
                const float2 bB = *(const float2*)&b1v[u0 + 8];
                unsigned a[4][4];
                #pragma unroll
                for (int mt = 0; mt < 4; mt++) {
                    const float x0 = xs[2 * mt], x1 = xs[2 * mt + 1];
                    a[mt][0] = h2u(fmaxf(x0 * wA.x + bA.x, 0.f),
                                   fmaxf(x0 * wA.y + bA.y, 0.f));
                    a[mt][1] = h2u(fmaxf(x1 * wA.x + bA.x, 0.f),
                                   fmaxf(x1 * wA.y + bA.y, 0.f));
                    a[mt][2] = h2u(fmaxf(x0 * wB.x + bB.x, 0.f),
                                   fmaxf(x0 * wB.y + bB.y, 0.f));
                    a[mt][3] = h2u(fmaxf(x1 * wB.x + bB.x, 0.f),
                                   fmaxf(x1 * wB.y + bB.y, 0.f));
                }
                #pragma unroll
                for (int mt = 0; mt < 4; mt++) {
                    mma_f16(acc[mt][0], a[mt], bq4[cur][0].x, bq4[cur][0].y);
                    mma_f16(acc[mt][1], a[mt], bq4[cur][0].z, bq4[cur][0].w);
                    mma_f16(acc[mt][2], a[mt], bq4[cur][1].x, bq4[cur][1].y);
                    mma_f16(acc[mt][3], a[mt], bq4[cur][1].z, bq4[cur][1].w);
                }
            }
        }
    }

    // Ring prologue: async-stage GEMM2 B k-tiles 0..2 (land during LN phase).
    {
        const unsigned wring = u_ring + (unsigned)(w * 4096 + lane * 32);
        #pragma unroll
        for (int i = 0; i < 3; i++) {
            const char* src = W2B + i * 8192 + w * 1024 + lane * 32;
            cp16(wring + (unsigned)(i * 1024), src);
            cp16(wring + (unsigned)(i * 1024) + 16u, src + 16);
            cp_commit();
        }
    }

    __syncthreads();   // (1) sAdd ready

    // Phase 3a: add staged (bias+phone+midi) from smem, per-row partial sums.
    {
        #pragma unroll
        for (int mt = 0; mt < 4; mt++) {
            const int r0 = mt * 16 + gid;
            const int r1 = r0 + 8;
            float s0 = 0.f, ss0 = 0.f, s1 = 0.f, ss1 = 0.f;
            #pragma unroll
            for (int nt = 0; nt < 4; nt++) {
                const int col = n0w + nt * 8 + q * 2;
                const float2 a0 = __half22float2(*(const __half2*)&sAdd[r0 * SA2H + col]);
                const float2 a1 = __half22float2(*(const __half2*)&sAdd[r1 * SA2H + col]);
                float x0 = acc[mt][nt][0] + a0.x;
                float x1 = acc[mt][nt][1] + a0.y;
                float x2 = acc[mt][nt][2] + a1.x;
                float x3 = acc[mt][nt][3] + a1.y;
                acc[mt][nt][0] = x0; acc[mt][nt][1] = x1;
                acc[mt][nt][2] = x2; acc[mt][nt][3] = x3;
                s0 += x0 + x1; ss0 += x0 * x0 + x1 * x1;
                s1 += x2 + x3; ss1 += x2 * x2 + x3 * x3;
            }
            #pragma unroll
            for (int o = 1; o < 4; o <<= 1) {
                s0 += __shfl_xor_sync(0xffffffffu, s0, o);
                ss0 += __shfl_xor_sync(0xffffffffu, ss0, o);
                s1 += __shfl_xor_sync(0xffffffffu, s1, o);
                ss1 += __shfl_xor_sync(0xffffffffu, ss1, o);
            }
            if (q == 0) {
                sPS[r0 * PS_STRIDE + w] = make_float2(s0, ss0);
                sPS[r1 * PS_STRIDE + w] = make_float2(s1, ss1);
            }
        }
    }
    __syncthreads();   // (2) partials ready; all sAdd reads done

    // Phase 3b: finalize mu/rs per row (threads 0..63)
    if (tid < 64) {
        float s = 0.f, ss = 0.f;
        #pragma unroll
        for (int j = 0; j < 8; j++) {
            const float2 ps = sPS[tid * PS_STRIDE + j];
            s += ps.x; ss += ps.y;
        }
        const float mu = s * (1.f / 256.f);
        float var = ss * (1.f / 256.f) - mu * mu;
        var = fmaxf(var, 0.f);
        sMV[tid] = make_float2(mu, rsqrtf(var + EPS));
    }
    __syncthreads();   // (3) mu/rs ready; safe to overwrite sAdd with sA2

    // Phase 3c: apply LN + ReLU in-register, write half A2 tile
    {
        #pragma unroll
        for (int mt = 0; mt < 4; mt++) {
            const int r0 = mt * 16 + gid;
            const int r1 = r0 + 8;
            const float2 mv0 = sMV[r0];
            const float2 mv1 = sMV[r1];
            #pragma unroll
            for (int nt = 0; nt < 4; nt++) {
                const int col = n0w + nt * 8 + q * 2;
                const float2 gg = *(const float2*)&sg[col];
                const float2 bb = *(const float2*)&sb[col];
                float x0 = fmaxf((acc[mt][nt][0] - mv0.x) * mv0.y * gg.x + bb.x, 0.f);
                float x1 = fmaxf((acc[mt][nt][1] - mv0.x) * mv0.y * gg.y + bb.y, 0.f);
                float x2 = fmaxf((acc[mt][nt][2] - mv1.x) * mv1.y * gg.x + bb.x, 0.f);
                float x3 = fmaxf((acc[mt][nt][3] - mv1.x) * mv1.y * gg.y + bb.y, 0.f);
                *(__half2*)&sA2[r0 * SA2H + col] = __floats2half2_rn(x0, x1);
                *(__half2*)&sA2[r1 * SA2H + col] = __floats2half2_rn(x2, x3);
            }
        }
    }
    __syncthreads();   // (4) A2 ready

    #pragma unroll
    for (int mt = 0; mt < 4; mt++)
        #pragma unroll
        for (int nt = 0; nt < 4; nt++)
            #pragma unroll
            for (int e = 0; e < 4; e++) acc[mt][nt][e] = 0.f;

    // Phase 4: GEMM2 (K=256 -> 16 fp16 k-tiles), per-warp cp.async ring for B.
    // Invariant: at iteration kt, exactly 3 groups newer than kt's exist
    // (empty commits at the tail keep this true) -> wait_group 3 ensures
    // kt's data has landed.
    {
        const unsigned wring = u_ring + (unsigned)(w * 4096);
        const unsigned fragOff = (unsigned)(lane * 16);   // (gid*4+q)*16
        #pragma unroll
        for (int kt = 0; kt < 16; kt++) {
            if (kt < 13) {
                const char* src = W2B + (kt + 3) * 8192 + w * 1024 + lane * 32;
                const unsigned dst =
                    wring + (unsigned)(((kt + 3) & 3) * 1024 + lane * 32);
                cp16(dst, src);
                cp16(dst + 16u, src + 16);
            }
            cp_commit();
            cp_wait3();
            const unsigned slot = wring + (unsigned)((kt & 3) * 1024);
            const uint4 b0 = lds128(slot + fragOff);
            const uint4 b1 = lds128(slot + 512u + fragOff);
            unsigned a[4][4];
            #pragma unroll
            for (int mt = 0; mt < 4; mt++)
                ldsm_x4(a[mt][0], a[mt][1], a[mt][2], a[mt][3],
                        aBase2[mt] + (unsigned)(kt * 32));
            #pragma unroll
            for (int mt = 0; mt < 4; mt++) {
                mma_f16(acc[mt][0], a[mt], b0.x, b0.y);
                mma_f16(acc[mt][1], a[mt], b0.z, b0.w);
                mma_f16(acc[mt][2], a[mt], b1.x, b1.y);
                mma_f16(acc[mt][3], a[mt], b1.z, b1.w);
            }
        }
    }

    // Phase 5: write output (+proj_b2)
    #pragma unroll
    for (int mt = 0; mt < 4; mt++) {
        const int row = mt * 16 + gid;
        #pragma unroll
        for (int nt = 0; nt < 4; nt++) {
            const int col = n0w + nt * 8 + q * 2;
            const float b2a = sb2[col];
            const float b2b = sb2[col + 1];
            if (base + row < npos)
                *(float2*)&out[(size_t)(base + row) * 256 + col] =
                    make_float2(acc[mt][nt][0] + b2a, acc[mt][nt][1] + b2b);
            if (base + row + 8 < npos)
                *(float2*)&out[(size_t)(base + row + 8) * 256 + col] =
                    make_float2(acc[mt][nt][2] + b2a, acc[mt][nt][3] + b2b);
        }
    }
}

extern "C" void kernel_launch(void* const* d_in, const int* in_sizes, int n_in,
                              void* d_out, int out_size) {
    const float* f0          = (const float*)d_in[0];
    const int*   phone       = (const int*)  d_in[1];
    const float* duration    = (const float*)d_in[2];
    const int*   midi        = (const int*)  d_in[3];
    const float* f0_w1       = (const float*)d_in[4];
    const float* f0_b1       = (const float*)d_in[5];
    const float* f0_w2       = (const float*)d_in[6];
    const float* f0_b2       = (const float*)d_in[7];
    const float* phone_table = (const float*)d_in[8];
    const float* midi_table  = (const float*)d_in[9];
    const float* dur_w1      = (const float*)d_in[10];
    const float* dur_b1      = (const float*)d_in[11];
    const float* dur_w2      = (const float*)d_in[12];
    const float* dur_b2      = (const float*)d_in[13];
    const float* proj_w1     = (const float*)d_in[14];
    const float* proj_b1     = (const float*)d_in[15];
    const float* ln_g        = (const float*)d_in[16];
    const float* ln_b        = (const float*)d_in[17];
    const float* proj_w2     = (const float*)d_in[18];
    const float* proj_b2     = (const float*)d_in[19];
    float* out = (float*)d_out;
    const int npos = in_sizes[0];

    precompute_kernel<<<549, 256>>>(f0_w2, f0_b2, phone_table, midi_table,
                                    dur_w2, dur_b2, proj_w1, proj_b1, proj_w2);

    const size_t smem_bytes =
        (size_t)(64 * SA2H) * sizeof(__half) +        // shared sA2/sAdd buffer
        (size_t)(8 * 4096) +                           // cp.async B ring
        (size_t)(64 * PS_STRIDE + 64) * sizeof(float2) +
        (size_t)(3 * 256) * sizeof(float) + 64;
    cudaFuncSetAttribute(cond_enc_mma_kernel,
                         cudaFuncAttributeMaxDynamicSharedMemorySize,
                         (int)smem_bytes);
    const int grid = (npos + TM - 1) / TM;
    cond_enc_mma_kernel<<<grid, 256, smem_bytes>>>(
        f0, phone, duration, midi, f0_w1, f0_b1, dur_w1, dur_b1,
        ln_g, ln_b, proj_b2, out, npos);
}